// round 8
// baseline (speedup 1.0000x reference)
#include <cuda_runtime.h>
#include <cuda_fp16.h>
#include <cstddef>
#include <cstdint>

#define H 64
#define NGn 100000
#define NDn 30000
#define Mn (NGn + NDn)

// fixed-stride adjacency buckets (degrees: gene ~Bin mean 15 max~34; disease mean 50 max~82)
#define GS 96
#define DS 192
#define GOFF (NGn * GS)

// -------- scratch --------
__device__ int g_deg[Mn];
__device__ __align__(16) int g_adj[(size_t)NGn * GS + (size_t)NDn * DS];   // 61.4MB
__device__ __half2 g_geneH[(size_t)NGn * 32];
__device__ __half2 g_disH [(size_t)NDn * 32];
__device__ __half2 g_hgH  [(size_t)NGn * 32];
__device__ __half2 g_hdH  [(size_t)NDn * 32];
__device__ __half2 g_mGH  [(size_t)NGn * 32];
__device__ __half2 g_mDH  [(size_t)NDn * 32];

// -------- helpers --------
__device__ __forceinline__ uint32_t packh2(float a, float b) {
    __half2 h = __floats2half2_rn(a, b);
    return *reinterpret_cast<uint32_t*>(&h);
}
__device__ __forceinline__ void mma16(float c[4],
                                      uint32_t a0, uint32_t a1, uint32_t a2, uint32_t a3,
                                      uint32_t b0, uint32_t b1) {
    asm volatile(
        "mma.sync.aligned.m16n8k16.row.col.f32.f16.f16.f32 "
        "{%0,%1,%2,%3},{%4,%5,%6,%7},{%8,%9},{%0,%1,%2,%3};"
        : "+f"(c[0]), "+f"(c[1]), "+f"(c[2]), "+f"(c[3])
        : "r"(a0), "r"(a1), "r"(a2), "r"(a3), "r"(b0), "r"(b1));
}
__device__ __forceinline__ void acc_u4(float2& a0, float2& a1, float2& a2, float2& a3,
                                       uint4 v) {
    const __half2* h = (const __half2*)&v;
    float2 f0 = __half22float2(h[0]);
    float2 f1 = __half22float2(h[1]);
    float2 f2 = __half22float2(h[2]);
    float2 f3 = __half22float2(h[3]);
    a0.x += f0.x; a0.y += f0.y;
    a1.x += f1.x; a1.y += f1.y;
    a2.x += f2.x; a2.y += f2.y;
    a3.x += f3.x; a3.y += f3.y;
}

// -------- fused prologue: zero deg + fp32->fp16 of both embedding tables --------
#define NZ4   (Mn / 4)
#define NG2   (NGn * 32)
#define ND2   (NDn * 32)
__global__ __launch_bounds__(256) void prep_kernel(
    int4* __restrict__ deg4,
    const float2* __restrict__ gene, __half2* __restrict__ geneH,
    const float2* __restrict__ dis,  __half2* __restrict__ disH)
{
    int i = blockIdx.x * blockDim.x + threadIdx.x;
    if (i < NZ4) {
        deg4[i] = make_int4(0, 0, 0, 0);
    } else if (i < NZ4 + NG2) {
        int j = i - NZ4;
        float2 v = gene[j];
        geneH[j] = __floats2half2_rn(v.x, v.y);
    } else if (i < NZ4 + NG2 + ND2) {
        int j = i - NZ4 - NG2;
        float2 v = dis[j];
        disH[j] = __floats2half2_rn(v.x, v.y);
    }
}

// -------- fused hist+scatter: atomic slot assignment into fixed-stride buckets --------
__global__ __launch_bounds__(256) void build_adj(
    const int* __restrict__ src, const int* __restrict__ dst,
    int* __restrict__ deg, int* __restrict__ adj, int ne)
{
    int e = blockIdx.x * blockDim.x + threadIdx.x;
    if (e >= ne) return;
    int s = src[e], d = dst[e];
    int p = atomicAdd(&deg[s], 1);
    if (p < GS) adj[s * GS + p] = d;
    int q = atomicAdd(&deg[NGn + d], 1);
    if (q < DS) adj[GOFF + (size_t)d * DS + q] = s;
}

// -------- warp-per-node gather-mean: pipelined idx quads, full-row uint4 loads --------
// lane = g*8+l: group g processes index-quads g, g+4, g+8, ...; sublane l covers
// 16B of the 128B fp16 row. Next quad prefetched before dependent feature loads.
__global__ __launch_bounds__(256) void gather_h(
    const uint4* __restrict__ xg4, const uint4* __restrict__ xd4,
    const int* __restrict__ degArr, const int* __restrict__ adj,
    uint4* __restrict__ outG, uint4* __restrict__ outD)
{
    int w = (blockIdx.x * blockDim.x + threadIdx.x) >> 5;
    if (w >= Mn) return;
    int lane = threadIdx.x & 31;
    int g = lane >> 3, l = lane & 7;
    bool isG = (w < NGn);
    const uint4* __restrict__ x4 = isG ? xd4 : xg4;
    int deg = __ldg(&degArr[w]);
    const int4* __restrict__ a4 = (const int4*)(adj +
        (isG ? (size_t)w * GS : (size_t)GOFF + (size_t)(w - NGn) * DS));

    float2 a0 = {0.f, 0.f}, a1 = {0.f, 0.f}, a2 = {0.f, 0.f}, a3 = {0.f, 0.f};

    int qi = g;
    bool valid = (qi * 4 < deg);
    int4 q = make_int4(0, 0, 0, 0);
    if (valid) q = __ldg(&a4[qi]);
    while (valid) {
        int qin = qi + 4;
        bool vn = (qin * 4 < deg);
        int4 qn = make_int4(0, 0, 0, 0);
        if (vn) qn = __ldg(&a4[qin]);          // prefetch next quad

        int rem = deg - qi * 4;                 // >= 1
        int i1 = (rem > 1) ? q.y : 0;
        int i2 = (rem > 2) ? q.z : 0;
        int i3 = (rem > 3) ? q.w : 0;
        uint4 v0 = __ldg(&x4[(size_t)q.x * 8 + l]);
        uint4 v1 = __ldg(&x4[(size_t)i1  * 8 + l]);
        uint4 v2 = __ldg(&x4[(size_t)i2  * 8 + l]);
        uint4 v3 = __ldg(&x4[(size_t)i3  * 8 + l]);
        acc_u4(a0, a1, a2, a3, v0);
        if (rem > 1) acc_u4(a0, a1, a2, a3, v1);
        if (rem > 2) acc_u4(a0, a1, a2, a3, v2);
        if (rem > 3) acc_u4(a0, a1, a2, a3, v3);

        qi = qin; q = qn; valid = vn;
    }

    // reduce the 4 group partials (butterfly over lane bits 3,4)
    #pragma unroll
    for (int o = 8; o <= 16; o <<= 1) {
        a0.x += __shfl_xor_sync(0xFFFFFFFFu, a0.x, o);
        a0.y += __shfl_xor_sync(0xFFFFFFFFu, a0.y, o);
        a1.x += __shfl_xor_sync(0xFFFFFFFFu, a1.x, o);
        a1.y += __shfl_xor_sync(0xFFFFFFFFu, a1.y, o);
        a2.x += __shfl_xor_sync(0xFFFFFFFFu, a2.x, o);
        a2.y += __shfl_xor_sync(0xFFFFFFFFu, a2.y, o);
        a3.x += __shfl_xor_sync(0xFFFFFFFFu, a3.x, o);
        a3.y += __shfl_xor_sync(0xFFFFFFFFu, a3.y, o);
    }
    if (g == 0) {
        float inv = 1.0f / fmaxf((float)deg, 1.0f);
        uint4 o;
        o.x = packh2(a0.x * inv, a0.y * inv);
        o.y = packh2(a1.x * inv, a1.y * inv);
        o.z = packh2(a2.x * inv, a2.y * inv);
        o.w = packh2(a3.x * inv, a3.y * inv);
        if (isG) outG[(size_t)w * 8 + l] = o;
        else     outD[(size_t)(w - NGn) * 8 + l] = o;
    }
}

// -------- persistent fused per-layer SAGE linear via fp16 mma (m16n8k16) --------
#define LIN_GRID 296
__global__ __launch_bounds__(256) void sage_mma2(
    const __half2* __restrict__ mDh, const __half2* __restrict__ xDh,
    const float* __restrict__ wDl, const float* __restrict__ wDr,
    const float* __restrict__ bDp, __half2* __restrict__ outDh, int nD,
    const __half2* __restrict__ mGh, const __half2* __restrict__ xGh,
    const float* __restrict__ wGl, const float* __restrict__ wGr,
    const float* __restrict__ bGp, __half2* __restrict__ outGh, int nG,
    int relu)
{
    __shared__ uint2 sB[8][8][32];   // 16KB packed fp16 W = [wl; wr]
    __shared__ float sBias[64];

    int nbD = (nD + 127) / 128;
    int nbG = (nG + 127) / 128;
    int split = (int)(((long long)LIN_GRID * nbD) / (nbD + nbG));
    if (split < 1) split = 1;
    bool isD = ((int)blockIdx.x < split);
    const __half2* mean = isD ? mDh : mGh;
    const __half2* x    = isD ? xDh : xGh;
    const float* wl     = isD ? wDl : wGl;
    const float* wr     = isD ? wDr : wGr;
    const float* bias   = isD ? bDp : bGp;
    __half2* out_h      = isD ? outDh : outGh;
    int n               = isD ? nD : nG;
    int nTiles          = isD ? nbD : nbG;
    int blk0            = isD ? blockIdx.x : (blockIdx.x - split);
    int nBlkSeg         = isD ? split : (LIN_GRID - split);

    int tid = threadIdx.x;

    for (int idx = tid; idx < 8 * 8 * 32; idx += 256) {
        int kc   = idx >> 8;
        int nt   = (idx >> 5) & 7;
        int lane = idx & 31;
        int t = lane & 3, g = lane >> 2;
        int c = nt * 8 + g;
        int k0 = kc * 16;
        int r0 = k0 + 2 * t, r2 = k0 + 2 * t + 8;
        float w00 = (r0 < 64)     ? wl[r0 * 64 + c]       : wr[(r0 - 64) * 64 + c];
        float w01 = (r0 + 1 < 64) ? wl[(r0 + 1) * 64 + c] : wr[(r0 - 63) * 64 + c];
        float w10 = (r2 < 64)     ? wl[r2 * 64 + c]       : wr[(r2 - 64) * 64 + c];
        float w11 = (r2 + 1 < 64) ? wl[(r2 + 1) * 64 + c] : wr[(r2 - 63) * 64 + c];
        sB[kc][nt][lane] = make_uint2(packh2(w00, w01), packh2(w10, w11));
    }
    if (tid < 64) sBias[tid] = bias[tid];
    __syncthreads();

    int warp = tid >> 5, lane = tid & 31;
    int t = lane & 3, g = lane >> 2;
    const uint32_t* meanU = (const uint32_t*)mean;
    const uint32_t* xU    = (const uint32_t*)x;

    for (int blk = blk0; blk < nTiles; blk += nBlkSeg) {
        int row0 = blk * 128 + warp * 16;
        int ra = row0 + g, rb = row0 + 8 + g;
        bool va = ra < n, vb = rb < n;
        size_t raL = (size_t)(va ? ra : 0);
        size_t rbL = (size_t)(vb ? rb : 0);

        float c_[8][4];
        #pragma unroll
        for (int nt = 0; nt < 8; nt++) {
            float b0 = sBias[nt * 8 + 2 * t];
            float b1 = sBias[nt * 8 + 2 * t + 1];
            c_[nt][0] = b0; c_[nt][1] = b1; c_[nt][2] = b0; c_[nt][3] = b1;
        }

        #pragma unroll
        for (int kc = 0; kc < 8; kc++) {
            const uint32_t* __restrict__ A = (kc < 4) ? meanU : xU;
            int base = (kc & 3) * 8;
            uint32_t a0 = __ldg(&A[raL * 32 + base + t]);
            uint32_t a1 = __ldg(&A[rbL * 32 + base + t]);
            uint32_t a2 = __ldg(&A[raL * 32 + base + t + 4]);
            uint32_t a3 = __ldg(&A[rbL * 32 + base + t + 4]);
            #pragma unroll
            for (int nt = 0; nt < 8; nt++) {
                uint2 B = sB[kc][nt][lane];
                mma16(c_[nt], a0, a1, a2, a3, B.x, B.y);
            }
        }

        #pragma unroll
        for (int nt = 0; nt < 8; nt++) {
            float c0 = c_[nt][0], c1 = c_[nt][1], c2 = c_[nt][2], c3 = c_[nt][3];
            if (relu) {
                c0 = fmaxf(c0, 0.f); c1 = fmaxf(c1, 0.f);
                c2 = fmaxf(c2, 0.f); c3 = fmaxf(c3, 0.f);
            }
            if (va) out_h[(size_t)ra * 32 + nt * 4 + t] = __floats2half2_rn(c0, c1);
            if (vb) out_h[(size_t)rb * 32 + nt * 4 + t] = __floats2half2_rn(c2, c3);
        }
    }
}

// -------- label-edge dot product over fp16 rows, fp32 accumulate --------
__global__ __launch_bounds__(256) void dot_h(
    const __half2* __restrict__ hg2, const __half2* __restrict__ hd2,
    const int* __restrict__ ls, const int* __restrict__ ld,
    float* __restrict__ out, int nl)
{
    int t = blockIdx.x * blockDim.x + threadIdx.x;
    int e = t >> 3;
    if (e >= nl) return;
    int lane = t & 7;
    int a = ls[e];
    int b = ld[e];
    const uint4* pg = (const uint4*)(hg2 + (size_t)a * 32);
    const uint4* pd = (const uint4*)(hd2 + (size_t)b * 32);
    uint4 G = __ldg(&pg[lane]);
    uint4 D = __ldg(&pd[lane]);

    float acc = 0.f;
    {
        float2 g0 = __half22float2(*(__half2*)&G.x), d0 = __half22float2(*(__half2*)&D.x);
        float2 g1 = __half22float2(*(__half2*)&G.y), d1 = __half22float2(*(__half2*)&D.y);
        float2 g2 = __half22float2(*(__half2*)&G.z), d2 = __half22float2(*(__half2*)&D.z);
        float2 g3 = __half22float2(*(__half2*)&G.w), d3 = __half22float2(*(__half2*)&D.w);
        acc = g0.x * d0.x + g0.y * d0.y + g1.x * d1.x + g1.y * d1.y
            + g2.x * d2.x + g2.y * d2.y + g3.x * d3.x + g3.y * d3.y;
    }
    acc += __shfl_down_sync(0xFFFFFFFFu, acc, 4);
    acc += __shfl_down_sync(0xFFFFFFFFu, acc, 2);
    acc += __shfl_down_sync(0xFFFFFFFFu, acc, 1);
    if (lane == 0) out[e] = acc;
}

extern "C" void kernel_launch(void* const* d_in, const int* in_sizes, int n_in,
                              void* d_out, int out_size)
{
    const float* gene = nullptr;
    const float* dis  = nullptr;
    const float* w[8] = {};
    const float* b[4] = {};
    const int*   edge[2] = {};
    const int*   lab[2]  = {};
    int wi = 0, bi = 0, ei = 0, li = 0;
    int ne = 0, nl = 0;

    for (int i = 0; i < n_in; i++) {
        int sz = in_sizes[i];
        if (sz == NGn * H)          gene = (const float*)d_in[i];
        else if (sz == NDn * H)     dis  = (const float*)d_in[i];
        else if (sz == H * H)       { if (wi < 8) w[wi++] = (const float*)d_in[i]; }
        else if (sz == H)           { if (bi < 4) b[bi++] = (const float*)d_in[i]; }
        else if (sz == 1500000)     { if (ei < 2) { edge[ei++] = (const int*)d_in[i]; ne = sz; } }
        else if (sz == 500000)      { if (li < 2) { lab[li++]  = (const int*)d_in[i]; nl = sz; } }
    }

    int *deg, *adj;
    __half2 *geneH, *disH, *hgH, *hdH, *mGH, *mDH;
    cudaGetSymbolAddress((void**)&deg,   g_deg);
    cudaGetSymbolAddress((void**)&adj,   g_adj);
    cudaGetSymbolAddress((void**)&geneH, g_geneH);
    cudaGetSymbolAddress((void**)&disH,  g_disH);
    cudaGetSymbolAddress((void**)&hgH,   g_hgH);
    cudaGetSymbolAddress((void**)&hdH,   g_hdH);
    cudaGetSymbolAddress((void**)&mGH,   g_mGH);
    cudaGetSymbolAddress((void**)&mDH,   g_mDH);

    int egrid = (ne + 255) / 256;
    int ggrid = (Mn * 32 + 255) / 256;
    int prep_items = NZ4 + NG2 + ND2;

    // ---- prologue + adjacency build (2 launches, no scan) ----
    prep_kernel<<<(prep_items + 255) / 256, 256>>>(
        (int4*)deg, (const float2*)gene, geneH, (const float2*)dis, disH);
    build_adj<<<egrid, 256>>>(edge[0], edge[1], deg, adj, ne);

    // ---- layer 1 ----
    gather_h<<<ggrid, 256>>>((const uint4*)geneH, (const uint4*)disH, deg, adj,
                             (uint4*)mGH, (uint4*)mDH);
    sage_mma2<<<LIN_GRID, 256>>>(mDH, disH, w[0], w[1], b[0], hdH, NDn,
                                 mGH, geneH, w[2], w[3], b[1], hgH, NGn, 1);

    // ---- layer 2 (fp16 outputs written in-place over hgH/hdH) ----
    gather_h<<<ggrid, 256>>>((const uint4*)hgH, (const uint4*)hdH, deg, adj,
                             (uint4*)mGH, (uint4*)mDH);
    sage_mma2<<<LIN_GRID, 256>>>(mDH, hdH, w[4], w[5], b[2], hdH, NDn,
                                 mGH, hgH, w[6], w[7], b[3], hgH, NGn, 0);

    // ---- classifier (fp16 rows, fp32 accumulate) ----
    int dot_grid = (nl * 8 + 255) / 256;
    dot_h<<<dot_grid, 256>>>(hgH, hdH, lab[0], lab[1], (float*)d_out, nl);
}

// round 9
// speedup vs baseline: 1.0939x; 1.0939x over previous
#include <cuda_runtime.h>
#include <cuda_fp16.h>
#include <cstddef>
#include <cstdint>

#define H 64
#define NGn 100000
#define NDn 30000
#define Mn (NGn + NDn)
#define NEmax 1500000
#define SCAN_B 1024
#define NBLK ((Mn + SCAN_B - 1) / SCAN_B)   // 127

// -------- scratch --------
__device__ int   g_deg [Mn];
__device__ int   g_incl[Mn];
__device__ int   g_off [Mn + 1];
__device__ int   g_cur [Mn];
__device__ int   g_part[256];
__device__ __align__(16) int g_adj [2 * NEmax];
__device__ __half2 g_geneH[(size_t)NGn * 32];
__device__ __half2 g_disH [(size_t)NDn * 32];
__device__ __half2 g_hgH  [(size_t)NGn * 32];
__device__ __half2 g_hdH  [(size_t)NDn * 32];
__device__ __half2 g_mGH  [(size_t)NGn * 32];
__device__ __half2 g_mDH  [(size_t)NDn * 32];

// -------- helpers --------
__device__ __forceinline__ uint32_t packh2(float a, float b) {
    __half2 h = __floats2half2_rn(a, b);
    return *reinterpret_cast<uint32_t*>(&h);
}
__device__ __forceinline__ void mma16(float c[4],
                                      uint32_t a0, uint32_t a1, uint32_t a2, uint32_t a3,
                                      uint32_t b0, uint32_t b1) {
    asm volatile(
        "mma.sync.aligned.m16n8k16.row.col.f32.f16.f16.f32 "
        "{%0,%1,%2,%3},{%4,%5,%6,%7},{%8,%9},{%0,%1,%2,%3};"
        : "+f"(c[0]), "+f"(c[1]), "+f"(c[2]), "+f"(c[3])
        : "r"(a0), "r"(a1), "r"(a2), "r"(a3), "r"(b0), "r"(b1));
}
__device__ __forceinline__ void acc_u4(float2& a0, float2& a1, float2& a2, float2& a3,
                                       uint4 v) {
    const __half2* h = (const __half2*)&v;
    float2 f0 = __half22float2(h[0]);
    float2 f1 = __half22float2(h[1]);
    float2 f2 = __half22float2(h[2]);
    float2 f3 = __half22float2(h[3]);
    a0.x += f0.x; a0.y += f0.y;
    a1.x += f1.x; a1.y += f1.y;
    a2.x += f2.x; a2.y += f2.y;
    a3.x += f3.x; a3.y += f3.y;
}

// -------- fused prologue: zero deg + fp32->fp16 of both embedding tables --------
#define NZ4   (Mn / 4)
#define NG2   (NGn * 32)
#define ND2   (NDn * 32)
__global__ __launch_bounds__(256) void prep_kernel(
    int4* __restrict__ deg4,
    const float2* __restrict__ gene, __half2* __restrict__ geneH,
    const float2* __restrict__ dis,  __half2* __restrict__ disH)
{
    int i = blockIdx.x * blockDim.x + threadIdx.x;
    if (i < NZ4) {
        deg4[i] = make_int4(0, 0, 0, 0);
    } else if (i < NZ4 + NG2) {
        int j = i - NZ4;
        float2 v = gene[j];
        geneH[j] = __floats2half2_rn(v.x, v.y);
    } else if (i < NZ4 + NG2 + ND2) {
        int j = i - NZ4 - NG2;
        float2 v = dis[j];
        disH[j] = __floats2half2_rn(v.x, v.y);
    }
}

// -------- CSR build --------
__global__ void hist_kernel(const int* __restrict__ src, const int* __restrict__ dst,
                            int* __restrict__ deg, int ne) {
    int e = blockIdx.x * blockDim.x + threadIdx.x;
    if (e >= ne) return;
    atomicAdd(&deg[src[e]], 1);
    atomicAdd(&deg[NGn + dst[e]], 1);
}

__global__ __launch_bounds__(1024) void scan1(const int* __restrict__ deg,
                                              int* __restrict__ incl,
                                              int* __restrict__ part, int n) {
    __shared__ int ws[32];
    int i = blockIdx.x * SCAN_B + threadIdx.x;
    int v = (i < n) ? deg[i] : 0;
    int x = v;
    #pragma unroll
    for (int o = 1; o < 32; o <<= 1) {
        int y = __shfl_up_sync(0xFFFFFFFFu, x, o);
        if ((threadIdx.x & 31) >= o) x += y;
    }
    if ((threadIdx.x & 31) == 31) ws[threadIdx.x >> 5] = x;
    __syncthreads();
    if (threadIdx.x < 32) {
        int y = ws[threadIdx.x];
        #pragma unroll
        for (int o = 1; o < 32; o <<= 1) {
            int z = __shfl_up_sync(0xFFFFFFFFu, y, o);
            if (threadIdx.x >= o) y += z;
        }
        ws[threadIdx.x] = y;
    }
    __syncthreads();
    if (threadIdx.x >= 32) x += ws[(threadIdx.x >> 5) - 1];
    if (i < n) incl[i] = x;
    if (threadIdx.x == 1023) part[blockIdx.x] = x;
}

__global__ __launch_bounds__(1024) void scan23(
    const int* __restrict__ incl, const int* __restrict__ deg,
    const int* __restrict__ part,
    int* __restrict__ off, int* __restrict__ cur, int n)
{
    __shared__ int sp[128];
    __shared__ int ws[4];
    int t = threadIdx.x;
    int x = 0, v = 0;
    if (t < 128) {
        v = (t < NBLK) ? part[t] : 0;
        x = v;
        #pragma unroll
        for (int o = 1; o < 32; o <<= 1) {
            int y = __shfl_up_sync(0xFFFFFFFFu, x, o);
            if ((t & 31) >= o) x += y;
        }
        if ((t & 31) == 31) ws[t >> 5] = x;
    }
    __syncthreads();
    if (t < 128) {
        int add = 0;
        for (int w = 0; w < (t >> 5); w++) add += ws[w];
        sp[t] = x + add - v;
    }
    __syncthreads();
    int i = blockIdx.x * SCAN_B + t;
    if (i < n) {
        int inc = incl[i] + sp[blockIdx.x];
        off[i + 1] = inc;
        cur[i] = inc - deg[i];
        if (i == 0) off[0] = 0;
    }
}

__global__ void scatter_kernel(const int* __restrict__ src, const int* __restrict__ dst,
                               int* __restrict__ cur, int* __restrict__ adj, int ne) {
    int e = blockIdx.x * blockDim.x + threadIdx.x;
    if (e >= ne) return;
    int s = src[e], d = dst[e];
    int p = atomicAdd(&cur[s], 1);        adj[p] = d;
    int q = atomicAdd(&cur[NGn + d], 1);  adj[q] = s;
}

// -------- warp-per-node gather-mean: 8-lane groups cover full rows (uint4) --------
__global__ __launch_bounds__(256) void gather_h(
    const uint4* __restrict__ xg4, const uint4* __restrict__ xd4,
    const int* __restrict__ off, const int* __restrict__ adj,
    uint4* __restrict__ outG, uint4* __restrict__ outD)
{
    int w = (blockIdx.x * blockDim.x + threadIdx.x) >> 5;
    if (w >= Mn) return;
    int lane = threadIdx.x & 31;
    int g = lane >> 3, l = lane & 7;
    int beg = off[w], end = off[w + 1];
    const uint4* __restrict__ x4 = (w < NGn) ? xd4 : xg4;

    float2 a0 = {0.f, 0.f}, a1 = {0.f, 0.f}, a2 = {0.f, 0.f}, a3 = {0.f, 0.f};
    int deg = end - beg;
    if (deg > 0) {
        int j = beg;
        for (; j + 8 <= end; j += 8) {
            int n0 = __ldg(&adj[j + g]);
            int n1 = __ldg(&adj[j + 4 + g]);
            uint4 v0 = __ldg(&x4[(size_t)n0 * 8 + l]);
            uint4 v1 = __ldg(&x4[(size_t)n1 * 8 + l]);
            acc_u4(a0, a1, a2, a3, v0);
            acc_u4(a0, a1, a2, a3, v1);
        }
        for (; j < end; j += 4) {
            int k = j + g;
            bool p = k < end;
            int nn = __ldg(&adj[p ? k : beg]);
            uint4 v = __ldg(&x4[(size_t)nn * 8 + l]);
            if (p) acc_u4(a0, a1, a2, a3, v);
        }
    }
    #pragma unroll
    for (int o = 8; o <= 16; o <<= 1) {
        a0.x += __shfl_xor_sync(0xFFFFFFFFu, a0.x, o);
        a0.y += __shfl_xor_sync(0xFFFFFFFFu, a0.y, o);
        a1.x += __shfl_xor_sync(0xFFFFFFFFu, a1.x, o);
        a1.y += __shfl_xor_sync(0xFFFFFFFFu, a1.y, o);
        a2.x += __shfl_xor_sync(0xFFFFFFFFu, a2.x, o);
        a2.y += __shfl_xor_sync(0xFFFFFFFFu, a2.y, o);
        a3.x += __shfl_xor_sync(0xFFFFFFFFu, a3.x, o);
        a3.y += __shfl_xor_sync(0xFFFFFFFFu, a3.y, o);
    }
    if (g == 0) {
        float inv = 1.0f / fmaxf((float)deg, 1.0f);
        uint4 o;
        o.x = packh2(a0.x * inv, a0.y * inv);
        o.y = packh2(a1.x * inv, a1.y * inv);
        o.z = packh2(a2.x * inv, a2.y * inv);
        o.w = packh2(a3.x * inv, a3.y * inv);
        if (w < NGn) outG[(size_t)w * 8 + l] = o;
        else         outD[(size_t)(w - NGn) * 8 + l] = o;
    }
}

// -------- persistent fused per-layer SAGE linear via fp16 mma (m16n8k16) --------
// 4 CTAs/SM (was 2): occupancy was the binding constraint (ncu: occ=22.5%, issue=13%).
#define LIN_GRID 592
__global__ __launch_bounds__(256) void sage_mma2(
    const __half2* __restrict__ mDh, const __half2* __restrict__ xDh,
    const float* __restrict__ wDl, const float* __restrict__ wDr,
    const float* __restrict__ bDp, __half2* __restrict__ outDh, int nD,
    const __half2* __restrict__ mGh, const __half2* __restrict__ xGh,
    const float* __restrict__ wGl, const float* __restrict__ wGr,
    const float* __restrict__ bGp, __half2* __restrict__ outGh, int nG,
    int relu)
{
    __shared__ uint2 sB[8][8][32];   // 16KB packed fp16 W = [wl; wr]
    __shared__ float sBias[64];

    int nbD = (nD + 127) / 128;
    int nbG = (nG + 127) / 128;
    int split = (int)(((long long)LIN_GRID * nbD) / (nbD + nbG));
    if (split < 1) split = 1;
    bool isD = ((int)blockIdx.x < split);
    const __half2* mean = isD ? mDh : mGh;
    const __half2* x    = isD ? xDh : xGh;
    const float* wl     = isD ? wDl : wGl;
    const float* wr     = isD ? wDr : wGr;
    const float* bias   = isD ? bDp : bGp;
    __half2* out_h      = isD ? outDh : outGh;
    int n               = isD ? nD : nG;
    int nTiles          = isD ? nbD : nbG;
    int blk0            = isD ? blockIdx.x : (blockIdx.x - split);
    int nBlkSeg         = isD ? split : (LIN_GRID - split);

    int tid = threadIdx.x;

    for (int idx = tid; idx < 8 * 8 * 32; idx += 256) {
        int kc   = idx >> 8;
        int nt   = (idx >> 5) & 7;
        int lane = idx & 31;
        int t = lane & 3, g = lane >> 2;
        int c = nt * 8 + g;
        int k0 = kc * 16;
        int r0 = k0 + 2 * t, r2 = k0 + 2 * t + 8;
        float w00 = (r0 < 64)     ? wl[r0 * 64 + c]       : wr[(r0 - 64) * 64 + c];
        float w01 = (r0 + 1 < 64) ? wl[(r0 + 1) * 64 + c] : wr[(r0 - 63) * 64 + c];
        float w10 = (r2 < 64)     ? wl[r2 * 64 + c]       : wr[(r2 - 64) * 64 + c];
        float w11 = (r2 + 1 < 64) ? wl[(r2 + 1) * 64 + c] : wr[(r2 - 63) * 64 + c];
        sB[kc][nt][lane] = make_uint2(packh2(w00, w01), packh2(w10, w11));
    }
    if (tid < 64) sBias[tid] = bias[tid];
    __syncthreads();

    int warp = tid >> 5, lane = tid & 31;
    int t = lane & 3, g = lane >> 2;
    const uint32_t* meanU = (const uint32_t*)mean;
    const uint32_t* xU    = (const uint32_t*)x;

    for (int blk = blk0; blk < nTiles; blk += nBlkSeg) {
        int row0 = blk * 128 + warp * 16;
        int ra = row0 + g, rb = row0 + 8 + g;
        bool va = ra < n, vb = rb < n;
        size_t raL = (size_t)(va ? ra : 0);
        size_t rbL = (size_t)(vb ? rb : 0);

        float c_[8][4];
        #pragma unroll
        for (int nt = 0; nt < 8; nt++) {
            float b0 = sBias[nt * 8 + 2 * t];
            float b1 = sBias[nt * 8 + 2 * t + 1];
            c_[nt][0] = b0; c_[nt][1] = b1; c_[nt][2] = b0; c_[nt][3] = b1;
        }

        #pragma unroll
        for (int kc = 0; kc < 8; kc++) {
            const uint32_t* __restrict__ A = (kc < 4) ? meanU : xU;
            int base = (kc & 3) * 8;
            uint32_t a0 = __ldg(&A[raL * 32 + base + t]);
            uint32_t a1 = __ldg(&A[rbL * 32 + base + t]);
            uint32_t a2 = __ldg(&A[raL * 32 + base + t + 4]);
            uint32_t a3 = __ldg(&A[rbL * 32 + base + t + 4]);
            #pragma unroll
            for (int nt = 0; nt < 8; nt++) {
                uint2 B = sB[kc][nt][lane];
                mma16(c_[nt], a0, a1, a2, a3, B.x, B.y);
            }
        }

        #pragma unroll
        for (int nt = 0; nt < 8; nt++) {
            float c0 = c_[nt][0], c1 = c_[nt][1], c2 = c_[nt][2], c3 = c_[nt][3];
            if (relu) {
                c0 = fmaxf(c0, 0.f); c1 = fmaxf(c1, 0.f);
                c2 = fmaxf(c2, 0.f); c3 = fmaxf(c3, 0.f);
            }
            if (va) out_h[(size_t)ra * 32 + nt * 4 + t] = __floats2half2_rn(c0, c1);
            if (vb) out_h[(size_t)rb * 32 + nt * 4 + t] = __floats2half2_rn(c2, c3);
        }
    }
}

// -------- label-edge dot product over fp16 rows, fp32 accumulate --------
__global__ __launch_bounds__(256) void dot_h(
    const __half2* __restrict__ hg2, const __half2* __restrict__ hd2,
    const int* __restrict__ ls, const int* __restrict__ ld,
    float* __restrict__ out, int nl)
{
    int t = blockIdx.x * blockDim.x + threadIdx.x;
    int e = t >> 3;
    if (e >= nl) return;
    int lane = t & 7;
    int a = ls[e];
    int b = ld[e];
    const uint4* pg = (const uint4*)(hg2 + (size_t)a * 32);
    const uint4* pd = (const uint4*)(hd2 + (size_t)b * 32);
    uint4 G = __ldg(&pg[lane]);
    uint4 D = __ldg(&pd[lane]);

    float acc = 0.f;
    {
        float2 g0 = __half22float2(*(__half2*)&G.x), d0 = __half22float2(*(__half2*)&D.x);
        float2 g1 = __half22float2(*(__half2*)&G.y), d1 = __half22float2(*(__half2*)&D.y);
        float2 g2 = __half22float2(*(__half2*)&G.z), d2 = __half22float2(*(__half2*)&D.z);
        float2 g3 = __half22float2(*(__half2*)&G.w), d3 = __half22float2(*(__half2*)&D.w);
        acc = g0.x * d0.x + g0.y * d0.y + g1.x * d1.x + g1.y * d1.y
            + g2.x * d2.x + g2.y * d2.y + g3.x * d3.x + g3.y * d3.y;
    }
    acc += __shfl_down_sync(0xFFFFFFFFu, acc, 4);
    acc += __shfl_down_sync(0xFFFFFFFFu, acc, 2);
    acc += __shfl_down_sync(0xFFFFFFFFu, acc, 1);
    if (lane == 0) out[e] = acc;
}

extern "C" void kernel_launch(void* const* d_in, const int* in_sizes, int n_in,
                              void* d_out, int out_size)
{
    const float* gene = nullptr;
    const float* dis  = nullptr;
    const float* w[8] = {};
    const float* b[4] = {};
    const int*   edge[2] = {};
    const int*   lab[2]  = {};
    int wi = 0, bi = 0, ei = 0, li = 0;
    int ne = 0, nl = 0;

    for (int i = 0; i < n_in; i++) {
        int sz = in_sizes[i];
        if (sz == NGn * H)          gene = (const float*)d_in[i];
        else if (sz == NDn * H)     dis  = (const float*)d_in[i];
        else if (sz == H * H)       { if (wi < 8) w[wi++] = (const float*)d_in[i]; }
        else if (sz == H)           { if (bi < 4) b[bi++] = (const float*)d_in[i]; }
        else if (sz == 1500000)     { if (ei < 2) { edge[ei++] = (const int*)d_in[i]; ne = sz; } }
        else if (sz == 500000)      { if (li < 2) { lab[li++]  = (const int*)d_in[i]; nl = sz; } }
    }

    int *deg, *incl, *off, *cur, *part, *adj;
    __half2 *geneH, *disH, *hgH, *hdH, *mGH, *mDH;
    cudaGetSymbolAddress((void**)&deg,   g_deg);
    cudaGetSymbolAddress((void**)&incl,  g_incl);
    cudaGetSymbolAddress((void**)&off,   g_off);
    cudaGetSymbolAddress((void**)&cur,   g_cur);
    cudaGetSymbolAddress((void**)&part,  g_part);
    cudaGetSymbolAddress((void**)&adj,   g_adj);
    cudaGetSymbolAddress((void**)&geneH, g_geneH);
    cudaGetSymbolAddress((void**)&disH,  g_disH);
    cudaGetSymbolAddress((void**)&hgH,   g_hgH);
    cudaGetSymbolAddress((void**)&hdH,   g_hdH);
    cudaGetSymbolAddress((void**)&mGH,   g_mGH);
    cudaGetSymbolAddress((void**)&mDH,   g_mDH);

    int egrid = (ne + 255) / 256;
    int ggrid = (Mn * 32 + 255) / 256;
    int prep_items = NZ4 + NG2 + ND2;

    // ---- prologue + CSR build ----
    prep_kernel<<<(prep_items + 255) / 256, 256>>>(
        (int4*)deg, (const float2*)gene, geneH, (const float2*)dis, disH);
    hist_kernel<<<egrid, 256>>>(edge[0], edge[1], deg, ne);
    scan1<<<NBLK, 1024>>>(deg, incl, part, Mn);
    scan23<<<NBLK, 1024>>>(incl, deg, part, off, cur, Mn);
    scatter_kernel<<<egrid, 256>>>(edge[0], edge[1], cur, adj, ne);

    // ---- layer 1 ----
    gather_h<<<ggrid, 256>>>((const uint4*)geneH, (const uint4*)disH, off, adj,
                             (uint4*)mGH, (uint4*)mDH);
    sage_mma2<<<LIN_GRID, 256>>>(mDH, disH, w[0], w[1], b[0], hdH, NDn,
                                 mGH, geneH, w[2], w[3], b[1], hgH, NGn, 1);

    // ---- layer 2 (fp16 outputs written in-place over hgH/hdH) ----
    gather_h<<<ggrid, 256>>>((const uint4*)hgH, (const uint4*)hdH, off, adj,
                             (uint4*)mGH, (uint4*)mDH);
    sage_mma2<<<LIN_GRID, 256>>>(mDH, hdH, w[4], w[5], b[2], hdH, NDn,
                                 mGH, hgH, w[6], w[7], b[3], hgH, NGn, 0);

    // ---- classifier (fp16 rows, fp32 accumulate) ----
    int dot_grid = (nl * 8 + 255) / 256;
    dot_h<<<dot_grid, 256>>>(hgH, hdH, lab[0], lab[1], (float*)d_out, nl);
}

// round 10
// speedup vs baseline: 1.1747x; 1.0739x over previous
#include <cuda_runtime.h>
#include <cuda_fp16.h>
#include <cstddef>
#include <cstdint>

#define H 64
#define NGn 100000
#define NDn 30000
#define Mn (NGn + NDn)
#define NEmax 1500000
#define SCAN_B 1024
#define NBLK ((Mn + SCAN_B - 1) / SCAN_B)   // 127

// -------- scratch --------
__device__ int   g_deg [Mn];
__device__ int   g_incl[Mn];
__device__ int   g_off [Mn + 1];
__device__ int   g_cur [Mn];
__device__ int   g_part[256];
__device__ __align__(16) int g_adj [2 * NEmax];
__device__ __half2 g_geneH[(size_t)NGn * 32];
__device__ __half2 g_disH [(size_t)NDn * 32];
__device__ __half2 g_hgH  [(size_t)NGn * 32];
__device__ __half2 g_hdH  [(size_t)NDn * 32];
__device__ __half2 g_mGH  [(size_t)NGn * 32];
__device__ __half2 g_mDH  [(size_t)NDn * 32];
__device__ uint2   g_wPack[4 * 2048];        // fp16 fragment-ordered weights, 4 (layer,side) pairs

// -------- helpers --------
__device__ __forceinline__ uint32_t packh2(float a, float b) {
    __half2 h = __floats2half2_rn(a, b);
    return *reinterpret_cast<uint32_t*>(&h);
}
__device__ __forceinline__ void mma16(float c[4],
                                      uint32_t a0, uint32_t a1, uint32_t a2, uint32_t a3,
                                      uint32_t b0, uint32_t b1) {
    asm volatile(
        "mma.sync.aligned.m16n8k16.row.col.f32.f16.f16.f32 "
        "{%0,%1,%2,%3},{%4,%5,%6,%7},{%8,%9},{%0,%1,%2,%3};"
        : "+f"(c[0]), "+f"(c[1]), "+f"(c[2]), "+f"(c[3])
        : "r"(a0), "r"(a1), "r"(a2), "r"(a3), "r"(b0), "r"(b1));
}
__device__ __forceinline__ void acc_u4(float2& a0, float2& a1, float2& a2, float2& a3,
                                       uint4 v) {
    const __half2* h = (const __half2*)&v;
    float2 f0 = __half22float2(h[0]);
    float2 f1 = __half22float2(h[1]);
    float2 f2 = __half22float2(h[2]);
    float2 f3 = __half22float2(h[3]);
    a0.x += f0.x; a0.y += f0.y;
    a1.x += f1.x; a1.y += f1.y;
    a2.x += f2.x; a2.y += f2.y;
    a3.x += f3.x; a3.y += f3.y;
}

// -------- fused prologue: zero deg + f2h conversions + weight fragment packing --------
#define NZ4   (Mn / 4)
#define NG2   (NGn * 32)
#define ND2   (NDn * 32)
#define NWP   (4 * 2048)
__global__ __launch_bounds__(256) void prep_kernel(
    int4* __restrict__ deg4,
    const float2* __restrict__ gene, __half2* __restrict__ geneH,
    const float2* __restrict__ dis,  __half2* __restrict__ disH,
    const float* __restrict__ w0, const float* __restrict__ w1,
    const float* __restrict__ w2, const float* __restrict__ w3,
    const float* __restrict__ w4, const float* __restrict__ w5,
    const float* __restrict__ w6, const float* __restrict__ w7,
    uint2* __restrict__ wPack)
{
    int i = blockIdx.x * blockDim.x + threadIdx.x;
    if (i < NZ4) {
        deg4[i] = make_int4(0, 0, 0, 0);
    } else if (i < NZ4 + NG2) {
        int j = i - NZ4;
        float2 v = gene[j];
        geneH[j] = __floats2half2_rn(v.x, v.y);
    } else if (i < NZ4 + NG2 + ND2) {
        int j = i - NZ4 - NG2;
        float2 v = dis[j];
        disH[j] = __floats2half2_rn(v.x, v.y);
    } else if (i < NZ4 + NG2 + ND2 + NWP) {
        int p = i - (NZ4 + NG2 + ND2);
        int pi  = p >> 11;           // 0..3: (L1,D) (L1,G) (L2,D) (L2,G)
        int rem = p & 2047;
        const float* wl;
        const float* wr;
        if      (pi == 0) { wl = w0; wr = w1; }
        else if (pi == 1) { wl = w2; wr = w3; }
        else if (pi == 2) { wl = w4; wr = w5; }
        else              { wl = w6; wr = w7; }
        int kc   = rem >> 8;
        int nt   = (rem >> 5) & 7;
        int lane = rem & 31;
        int t = lane & 3, g = lane >> 2;
        int c = nt * 8 + g;
        int k0 = kc * 16;
        int r0 = k0 + 2 * t, r2 = r0 + 8;
        float w00 = (r0 < 64)     ? wl[r0 * 64 + c]       : wr[(r0 - 64) * 64 + c];
        float w01 = (r0 + 1 < 64) ? wl[(r0 + 1) * 64 + c] : wr[(r0 - 63) * 64 + c];
        float w10 = (r2 < 64)     ? wl[r2 * 64 + c]       : wr[(r2 - 64) * 64 + c];
        float w11 = (r2 + 1 < 64) ? wl[(r2 + 1) * 64 + c] : wr[(r2 - 63) * 64 + c];
        wPack[p] = make_uint2(packh2(w00, w01), packh2(w10, w11));
    }
}

// -------- CSR build --------
__global__ void hist_kernel(const int* __restrict__ src, const int* __restrict__ dst,
                            int* __restrict__ deg, int ne) {
    int e = blockIdx.x * blockDim.x + threadIdx.x;
    if (e >= ne) return;
    atomicAdd(&deg[src[e]], 1);
    atomicAdd(&deg[NGn + dst[e]], 1);
}

__global__ __launch_bounds__(1024) void scan1(const int* __restrict__ deg,
                                              int* __restrict__ incl,
                                              int* __restrict__ part, int n) {
    __shared__ int ws[32];
    int i = blockIdx.x * SCAN_B + threadIdx.x;
    int v = (i < n) ? deg[i] : 0;
    int x = v;
    #pragma unroll
    for (int o = 1; o < 32; o <<= 1) {
        int y = __shfl_up_sync(0xFFFFFFFFu, x, o);
        if ((threadIdx.x & 31) >= o) x += y;
    }
    if ((threadIdx.x & 31) == 31) ws[threadIdx.x >> 5] = x;
    __syncthreads();
    if (threadIdx.x < 32) {
        int y = ws[threadIdx.x];
        #pragma unroll
        for (int o = 1; o < 32; o <<= 1) {
            int z = __shfl_up_sync(0xFFFFFFFFu, y, o);
            if (threadIdx.x >= o) y += z;
        }
        ws[threadIdx.x] = y;
    }
    __syncthreads();
    if (threadIdx.x >= 32) x += ws[(threadIdx.x >> 5) - 1];
    if (i < n) incl[i] = x;
    if (threadIdx.x == 1023) part[blockIdx.x] = x;
}

__global__ __launch_bounds__(1024) void scan23(
    const int* __restrict__ incl, const int* __restrict__ deg,
    const int* __restrict__ part,
    int* __restrict__ off, int* __restrict__ cur, int n)
{
    __shared__ int sp[128];
    __shared__ int ws[4];
    int t = threadIdx.x;
    int x = 0, v = 0;
    if (t < 128) {
        v = (t < NBLK) ? part[t] : 0;
        x = v;
        #pragma unroll
        for (int o = 1; o < 32; o <<= 1) {
            int y = __shfl_up_sync(0xFFFFFFFFu, x, o);
            if ((t & 31) >= o) x += y;
        }
        if ((t & 31) == 31) ws[t >> 5] = x;
    }
    __syncthreads();
    if (t < 128) {
        int add = 0;
        for (int w = 0; w < (t >> 5); w++) add += ws[w];
        sp[t] = x + add - v;
    }
    __syncthreads();
    int i = blockIdx.x * SCAN_B + t;
    if (i < n) {
        int inc = incl[i] + sp[blockIdx.x];
        off[i + 1] = inc;
        cur[i] = inc - deg[i];
        if (i == 0) off[0] = 0;
    }
}

__global__ void scatter_kernel(const int* __restrict__ src, const int* __restrict__ dst,
                               int* __restrict__ cur, int* __restrict__ adj, int ne) {
    int e = blockIdx.x * blockDim.x + threadIdx.x;
    if (e >= ne) return;
    int s = src[e], d = dst[e];
    int p = atomicAdd(&cur[s], 1);        adj[p] = d;
    int q = atomicAdd(&cur[NGn + d], 1);  adj[q] = s;
}

// -------- warp-per-node gather-mean: 8-lane groups cover full rows (uint4) --------
__global__ __launch_bounds__(256) void gather_h(
    const uint4* __restrict__ xg4, const uint4* __restrict__ xd4,
    const int* __restrict__ off, const int* __restrict__ adj,
    uint4* __restrict__ outG, uint4* __restrict__ outD)
{
    int w = (blockIdx.x * blockDim.x + threadIdx.x) >> 5;
    if (w >= Mn) return;
    int lane = threadIdx.x & 31;
    int g = lane >> 3, l = lane & 7;
    int beg = off[w], end = off[w + 1];
    const uint4* __restrict__ x4 = (w < NGn) ? xd4 : xg4;

    float2 a0 = {0.f, 0.f}, a1 = {0.f, 0.f}, a2 = {0.f, 0.f}, a3 = {0.f, 0.f};
    int deg = end - beg;
    if (deg > 0) {
        int j = beg;
        for (; j + 8 <= end; j += 8) {
            int n0 = __ldg(&adj[j + g]);
            int n1 = __ldg(&adj[j + 4 + g]);
            uint4 v0 = __ldg(&x4[(size_t)n0 * 8 + l]);
            uint4 v1 = __ldg(&x4[(size_t)n1 * 8 + l]);
            acc_u4(a0, a1, a2, a3, v0);
            acc_u4(a0, a1, a2, a3, v1);
        }
        for (; j < end; j += 4) {
            int k = j + g;
            bool p = k < end;
            int nn = __ldg(&adj[p ? k : beg]);
            uint4 v = __ldg(&x4[(size_t)nn * 8 + l]);
            if (p) acc_u4(a0, a1, a2, a3, v);
        }
    }
    #pragma unroll
    for (int o = 8; o <= 16; o <<= 1) {
        a0.x += __shfl_xor_sync(0xFFFFFFFFu, a0.x, o);
        a0.y += __shfl_xor_sync(0xFFFFFFFFu, a0.y, o);
        a1.x += __shfl_xor_sync(0xFFFFFFFFu, a1.x, o);
        a1.y += __shfl_xor_sync(0xFFFFFFFFu, a1.y, o);
        a2.x += __shfl_xor_sync(0xFFFFFFFFu, a2.x, o);
        a2.y += __shfl_xor_sync(0xFFFFFFFFu, a2.y, o);
        a3.x += __shfl_xor_sync(0xFFFFFFFFu, a3.x, o);
        a3.y += __shfl_xor_sync(0xFFFFFFFFu, a3.y, o);
    }
    if (g == 0) {
        float inv = 1.0f / fmaxf((float)deg, 1.0f);
        uint4 o;
        o.x = packh2(a0.x * inv, a0.y * inv);
        o.y = packh2(a1.x * inv, a1.y * inv);
        o.z = packh2(a2.x * inv, a2.y * inv);
        o.w = packh2(a3.x * inv, a3.y * inv);
        if (w < NGn) outG[(size_t)w * 8 + l] = o;
        else         outD[(size_t)(w - NGn) * 8 + l] = o;
    }
}

// -------- persistent per-layer SAGE linear: smem-staged A + pre-packed fp16 B --------
// Per 128-row tile: phase M stages mean rows (coalesced LDG.128 -> padded sA),
// kc 0-3 consume; phase X stages x rows, kc 4-7 consume. Fragment LDS is
// bank-conflict-free (144B row stride: banks {4g+t}).
#define LIN_GRID 592
__global__ __launch_bounds__(256) void sage_mma2(
    const uint4* __restrict__ mD4, const uint4* __restrict__ xD4,
    const uint2* __restrict__ wpD, const float* __restrict__ bDp,
    __half2* __restrict__ outDh, int nD,
    const uint4* __restrict__ mG4, const uint4* __restrict__ xG4,
    const uint2* __restrict__ wpG, const float* __restrict__ bGp,
    __half2* __restrict__ outGh, int nG,
    int relu)
{
    __shared__ uint2 sB[2048];           // 16KB fp16 fragment-ordered W
    __shared__ float sBias[64];
    __shared__ uint32_t sA[128][36];     // 18KB, 144B row stride (pad 32->36 words)

    int nbD = (nD + 127) / 128;
    int nbG = (nG + 127) / 128;
    int split = (int)(((long long)LIN_GRID * nbD) / (nbD + nbG));
    if (split < 1) split = 1;
    bool isD = ((int)blockIdx.x < split);
    const uint4* mean4  = isD ? mD4 : mG4;
    const uint4* x4     = isD ? xD4 : xG4;
    const uint2* wp     = isD ? wpD : wpG;
    const float* bias   = isD ? bDp : bGp;
    __half2* out_h      = isD ? outDh : outGh;
    int n               = isD ? nD : nG;
    int nTiles          = isD ? nbD : nbG;
    int blk0            = isD ? blockIdx.x : (blockIdx.x - split);
    int nBlkSeg         = isD ? split : (LIN_GRID - split);

    int tid = threadIdx.x;

    for (int i = tid; i < 2048; i += 256) sB[i] = __ldg(&wp[i]);
    if (tid < 64) sBias[tid] = bias[tid];

    int warp = tid >> 5, lane = tid & 31;
    int t = lane & 3, g = lane >> 2;
    int la = warp * 16 + g, lb = la + 8;

    for (int blk = blk0; blk < nTiles; blk += nBlkSeg) {
        int tileBase = blk * 128;
        int ra = tileBase + la, rb = tileBase + lb;
        bool va = ra < n, vb = rb < n;

        float c_[8][4];

        __syncthreads();   // previous tile's sA reads done; also covers sB/sBias first time
        // ---- stage mean tile ----
        #pragma unroll
        for (int r4 = 0; r4 < 4; r4++) {
            int flat = tid + r4 * 256;
            int row = flat >> 3, c4 = flat & 7;
            int gr = tileBase + row;
            uint4 v = __ldg(&mean4[(size_t)(gr < n ? gr : 0) * 8 + c4]);
            *(uint4*)&sA[row][c4 * 4] = v;
        }
        __syncthreads();

        #pragma unroll
        for (int nt = 0; nt < 8; nt++) {
            float b0 = sBias[nt * 8 + 2 * t];
            float b1 = sBias[nt * 8 + 2 * t + 1];
            c_[nt][0] = b0; c_[nt][1] = b1; c_[nt][2] = b0; c_[nt][3] = b1;
        }

        #pragma unroll
        for (int kc = 0; kc < 4; kc++) {
            int b8 = kc * 8;
            uint32_t a0 = sA[la][b8 + t];
            uint32_t a1 = sA[lb][b8 + t];
            uint32_t a2 = sA[la][b8 + t + 4];
            uint32_t a3 = sA[lb][b8 + t + 4];
            #pragma unroll
            for (int nt = 0; nt < 8; nt++) {
                uint2 B = sB[kc * 256 + nt * 32 + lane];
                mma16(c_[nt], a0, a1, a2, a3, B.x, B.y);
            }
        }

        __syncthreads();   // mean reads done
        // ---- stage x tile ----
        #pragma unroll
        for (int r4 = 0; r4 < 4; r4++) {
            int flat = tid + r4 * 256;
            int row = flat >> 3, c4 = flat & 7;
            int gr = tileBase + row;
            uint4 v = __ldg(&x4[(size_t)(gr < n ? gr : 0) * 8 + c4]);
            *(uint4*)&sA[row][c4 * 4] = v;
        }
        __syncthreads();

        #pragma unroll
        for (int kc = 4; kc < 8; kc++) {
            int b8 = (kc & 3) * 8;
            uint32_t a0 = sA[la][b8 + t];
            uint32_t a1 = sA[lb][b8 + t];
            uint32_t a2 = sA[la][b8 + t + 4];
            uint32_t a3 = sA[lb][b8 + t + 4];
            #pragma unroll
            for (int nt = 0; nt < 8; nt++) {
                uint2 B = sB[kc * 256 + nt * 32 + lane];
                mma16(c_[nt], a0, a1, a2, a3, B.x, B.y);
            }
        }

        // ---- epilogue ----
        #pragma unroll
        for (int nt = 0; nt < 8; nt++) {
            float c0 = c_[nt][0], c1 = c_[nt][1], c2 = c_[nt][2], c3 = c_[nt][3];
            if (relu) {
                c0 = fmaxf(c0, 0.f); c1 = fmaxf(c1, 0.f);
                c2 = fmaxf(c2, 0.f); c3 = fmaxf(c3, 0.f);
            }
            if (va) out_h[(size_t)ra * 32 + nt * 4 + t] = __floats2half2_rn(c0, c1);
            if (vb) out_h[(size_t)rb * 32 + nt * 4 + t] = __floats2half2_rn(c2, c3);
        }
    }
}

// -------- label-edge dot product over fp16 rows, fp32 accumulate --------
__global__ __launch_bounds__(256) void dot_h(
    const __half2* __restrict__ hg2, const __half2* __restrict__ hd2,
    const int* __restrict__ ls, const int* __restrict__ ld,
    float* __restrict__ out, int nl)
{
    int t = blockIdx.x * blockDim.x + threadIdx.x;
    int e = t >> 3;
    if (e >= nl) return;
    int lane = t & 7;
    int a = ls[e];
    int b = ld[e];
    const uint4* pg = (const uint4*)(hg2 + (size_t)a * 32);
    const uint4* pd = (const uint4*)(hd2 + (size_t)b * 32);
    uint4 G = __ldg(&pg[lane]);
    uint4 D = __ldg(&pd[lane]);

    float acc = 0.f;
    {
        float2 g0 = __half22float2(*(__half2*)&G.x), d0 = __half22float2(*(__half2*)&D.x);
        float2 g1 = __half22float2(*(__half2*)&G.y), d1 = __half22float2(*(__half2*)&D.y);
        float2 g2 = __half22float2(*(__half2*)&G.z), d2 = __half22float2(*(__half2*)&D.z);
        float2 g3 = __half22float2(*(__half2*)&G.w), d3 = __half22float2(*(__half2*)&D.w);
        acc = g0.x * d0.x + g0.y * d0.y + g1.x * d1.x + g1.y * d1.y
            + g2.x * d2.x + g2.y * d2.y + g3.x * d3.x + g3.y * d3.y;
    }
    acc += __shfl_down_sync(0xFFFFFFFFu, acc, 4);
    acc += __shfl_down_sync(0xFFFFFFFFu, acc, 2);
    acc += __shfl_down_sync(0xFFFFFFFFu, acc, 1);
    if (lane == 0) out[e] = acc;
}

extern "C" void kernel_launch(void* const* d_in, const int* in_sizes, int n_in,
                              void* d_out, int out_size)
{
    const float* gene = nullptr;
    const float* dis  = nullptr;
    const float* w[8] = {};
    const float* b[4] = {};
    const int*   edge[2] = {};
    const int*   lab[2]  = {};
    int wi = 0, bi = 0, ei = 0, li = 0;
    int ne = 0, nl = 0;

    for (int i = 0; i < n_in; i++) {
        int sz = in_sizes[i];
        if (sz == NGn * H)          gene = (const float*)d_in[i];
        else if (sz == NDn * H)     dis  = (const float*)d_in[i];
        else if (sz == H * H)       { if (wi < 8) w[wi++] = (const float*)d_in[i]; }
        else if (sz == H)           { if (bi < 4) b[bi++] = (const float*)d_in[i]; }
        else if (sz == 1500000)     { if (ei < 2) { edge[ei++] = (const int*)d_in[i]; ne = sz; } }
        else if (sz == 500000)      { if (li < 2) { lab[li++]  = (const int*)d_in[i]; nl = sz; } }
    }

    int *deg, *incl, *off, *cur, *part, *adj;
    __half2 *geneH, *disH, *hgH, *hdH, *mGH, *mDH;
    uint2 *wPack;
    cudaGetSymbolAddress((void**)&deg,   g_deg);
    cudaGetSymbolAddress((void**)&incl,  g_incl);
    cudaGetSymbolAddress((void**)&off,   g_off);
    cudaGetSymbolAddress((void**)&cur,   g_cur);
    cudaGetSymbolAddress((void**)&part,  g_part);
    cudaGetSymbolAddress((void**)&adj,   g_adj);
    cudaGetSymbolAddress((void**)&geneH, g_geneH);
    cudaGetSymbolAddress((void**)&disH,  g_disH);
    cudaGetSymbolAddress((void**)&hgH,   g_hgH);
    cudaGetSymbolAddress((void**)&hdH,   g_hdH);
    cudaGetSymbolAddress((void**)&mGH,   g_mGH);
    cudaGetSymbolAddress((void**)&mDH,   g_mDH);
    cudaGetSymbolAddress((void**)&wPack, g_wPack);

    int egrid = (ne + 255) / 256;
    int ggrid = (Mn * 32 + 255) / 256;
    int prep_items = NZ4 + NG2 + ND2 + NWP;

    // ---- prologue + CSR build ----
    prep_kernel<<<(prep_items + 255) / 256, 256>>>(
        (int4*)deg, (const float2*)gene, geneH, (const float2*)dis, disH,
        w[0], w[1], w[2], w[3], w[4], w[5], w[6], w[7], wPack);
    hist_kernel<<<egrid, 256>>>(edge[0], edge[1], deg, ne);
    scan1<<<NBLK, 1024>>>(deg, incl, part, Mn);
    scan23<<<NBLK, 1024>>>(incl, deg, part, off, cur, Mn);
    scatter_kernel<<<egrid, 256>>>(edge[0], edge[1], cur, adj, ne);

    // ---- layer 1 ----
    gather_h<<<ggrid, 256>>>((const uint4*)geneH, (const uint4*)disH, off, adj,
                             (uint4*)mGH, (uint4*)mDH);
    sage_mma2<<<LIN_GRID, 256>>>(
        (const uint4*)mDH, (const uint4*)disH,  wPack + 0,    b[0], hdH, NDn,
        (const uint4*)mGH, (const uint4*)geneH, wPack + 2048, b[1], hgH, NGn, 1);

    // ---- layer 2 (fp16 outputs written in-place over hgH/hdH) ----
    gather_h<<<ggrid, 256>>>((const uint4*)hgH, (const uint4*)hdH, off, adj,
                             (uint4*)mGH, (uint4*)mDH);
    sage_mma2<<<LIN_GRID, 256>>>(
        (const uint4*)mDH, (const uint4*)hdH, wPack + 4096, b[2], hdH, NDn,
        (const uint4*)mGH, (const uint4*)hgH, wPack + 6144, b[3], hgH, NGn, 0);

    // ---- classifier (fp16 rows, fp32 accumulate) ----
    int dot_grid = (nl * 8 + 255) / 256;
    dot_h<<<dot_grid, 256>>>(hgH, hdH, lab[0], lab[1], (float*)d_out, nl);
}

// round 11
// speedup vs baseline: 1.2149x; 1.0342x over previous
#include <cuda_runtime.h>
#include <cuda_fp16.h>
#include <cstddef>
#include <cstdint>

#define H 64
#define NGn 100000
#define NDn 30000
#define Mn (NGn + NDn)
#define NEmax 1500000
#define SCAN_B 1024
#define NBLK ((Mn + SCAN_B - 1) / SCAN_B)   // 127

// -------- scratch (zero-initialized at module load; deg/partf invariant:
//          zero at every kernel_launch entry, restored by scatter each call) --------
__device__ int   g_deg [Mn];
__device__ int   g_partf[128];               // lookback flags: (sum<<1)|1
__device__ int   g_off [Mn + 1];
__device__ int   g_cur [Mn];
__device__ __align__(16) int g_adj [2 * NEmax];
__device__ __half2 g_geneH[(size_t)NGn * 32];
__device__ __half2 g_disH [(size_t)NDn * 32];
__device__ __half2 g_hgH  [(size_t)NGn * 32];
__device__ __half2 g_hdH  [(size_t)NDn * 32];
__device__ __half2 g_mGH  [(size_t)NGn * 32];
__device__ __half2 g_mDH  [(size_t)NDn * 32];
__device__ uint2   g_wPack[4 * 2048];

// -------- helpers --------
__device__ __forceinline__ uint32_t packh2(float a, float b) {
    __half2 h = __floats2half2_rn(a, b);
    return *reinterpret_cast<uint32_t*>(&h);
}
__device__ __forceinline__ void mma16(float c[4],
                                      uint32_t a0, uint32_t a1, uint32_t a2, uint32_t a3,
                                      uint32_t b0, uint32_t b1) {
    asm volatile(
        "mma.sync.aligned.m16n8k16.row.col.f32.f16.f16.f32 "
        "{%0,%1,%2,%3},{%4,%5,%6,%7},{%8,%9},{%0,%1,%2,%3};"
        : "+f"(c[0]), "+f"(c[1]), "+f"(c[2]), "+f"(c[3])
        : "r"(a0), "r"(a1), "r"(a2), "r"(a3), "r"(b0), "r"(b1));
}
__device__ __forceinline__ void acc_u4(float2& a0, float2& a1, float2& a2, float2& a3,
                                       uint4 v) {
    const __half2* h = (const __half2*)&v;
    float2 f0 = __half22float2(h[0]);
    float2 f1 = __half22float2(h[1]);
    float2 f2 = __half22float2(h[2]);
    float2 f3 = __half22float2(h[3]);
    a0.x += f0.x; a0.y += f0.y;
    a1.x += f1.x; a1.y += f1.y;
    a2.x += f2.x; a2.y += f2.y;
    a3.x += f3.x; a3.y += f3.y;
}

// -------- fused prep (f2h + weight packing) + hist, block-range split --------
#define NG2   (NGn * 32)
#define ND2   (NDn * 32)
#define NWP   (4 * 2048)
#define PREP_ITEMS (NG2 + ND2 + NWP)
#define PREP_BLOCKS ((PREP_ITEMS + 255) / 256)
__global__ __launch_bounds__(256) void prep_hist(
    const float2* __restrict__ gene, __half2* __restrict__ geneH,
    const float2* __restrict__ dis,  __half2* __restrict__ disH,
    const float* __restrict__ w0, const float* __restrict__ w1,
    const float* __restrict__ w2, const float* __restrict__ w3,
    const float* __restrict__ w4, const float* __restrict__ w5,
    const float* __restrict__ w6, const float* __restrict__ w7,
    uint2* __restrict__ wPack,
    const int* __restrict__ src, const int* __restrict__ dst, int ne)
{
    int blk = blockIdx.x;
    if (blk < PREP_BLOCKS) {
        int i = blk * 256 + threadIdx.x;
        if (i < NG2) {
            float2 v = gene[i];
            geneH[i] = __floats2half2_rn(v.x, v.y);
        } else if (i < NG2 + ND2) {
            int j = i - NG2;
            float2 v = dis[j];
            disH[j] = __floats2half2_rn(v.x, v.y);
        } else if (i < PREP_ITEMS) {
            int p = i - (NG2 + ND2);
            int pi  = p >> 11;
            int rem = p & 2047;
            const float* wl;
            const float* wr;
            if      (pi == 0) { wl = w0; wr = w1; }
            else if (pi == 1) { wl = w2; wr = w3; }
            else if (pi == 2) { wl = w4; wr = w5; }
            else              { wl = w6; wr = w7; }
            int kc   = rem >> 8;
            int nt   = (rem >> 5) & 7;
            int lane = rem & 31;
            int t = lane & 3, g = lane >> 2;
            int c = nt * 8 + g;
            int k0 = kc * 16;
            int r0 = k0 + 2 * t, r2 = r0 + 8;
            float w00 = (r0 < 64)     ? wl[r0 * 64 + c]       : wr[(r0 - 64) * 64 + c];
            float w01 = (r0 + 1 < 64) ? wl[(r0 + 1) * 64 + c] : wr[(r0 - 63) * 64 + c];
            float w10 = (r2 < 64)     ? wl[r2 * 64 + c]       : wr[(r2 - 64) * 64 + c];
            float w11 = (r2 + 1 < 64) ? wl[(r2 + 1) * 64 + c] : wr[(r2 - 63) * 64 + c];
            wPack[p] = make_uint2(packh2(w00, w01), packh2(w10, w11));
        }
    } else {
        int e = (blk - PREP_BLOCKS) * 256 + threadIdx.x;
        if (e < ne) {
            atomicAdd(&g_deg[src[e]], 1);
            atomicAdd(&g_deg[NGn + dst[e]], 1);
        }
    }
}

// -------- single-pass scan with decoupled lookback (127 blocks, all resident) --------
__global__ __launch_bounds__(1024) void scan_fused(
    int* __restrict__ off, int* __restrict__ cur, int n)
{
    __shared__ int ws[32];
    __shared__ int sv[128];
    __shared__ int sExc;
    int bid = blockIdx.x;
    int tid = threadIdx.x;
    int i = bid * SCAN_B + tid;
    int v = (i < n) ? g_deg[i] : 0;
    int x = v;
    #pragma unroll
    for (int o = 1; o < 32; o <<= 1) {
        int y = __shfl_up_sync(0xFFFFFFFFu, x, o);
        if ((tid & 31) >= o) x += y;
    }
    if ((tid & 31) == 31) ws[tid >> 5] = x;
    __syncthreads();
    if (tid < 32) {
        int y = ws[tid];
        #pragma unroll
        for (int o = 1; o < 32; o <<= 1) {
            int z = __shfl_up_sync(0xFFFFFFFFu, y, o);
            if (tid >= o) y += z;
        }
        ws[tid] = y;
    }
    __syncthreads();
    if (tid >= 32) x += ws[(tid >> 5) - 1];
    // publish this block's total (inclusive of full tile) with flag bit
    if (tid == 1023) {
        atomicExch(&g_partf[bid], (x << 1) | 1);
    }
    if (tid < 128) sv[tid] = 0;
    __syncthreads();
    // lookback: thread t polls predecessor block t's partial
    if (tid < bid) {
        int p;
        do { p = *(volatile int*)&g_partf[tid]; } while ((p & 1) == 0);
        sv[tid] = p >> 1;
    }
    __syncthreads();
    if (tid < 64) sv[tid] += sv[tid + 64];
    __syncthreads();
    if (tid < 32) {
        int s = sv[tid] + sv[tid + 32];
        #pragma unroll
        for (int o = 16; o; o >>= 1) s += __shfl_down_sync(0xFFFFFFFFu, s, o);
        if (tid == 0) sExc = s;
    }
    __syncthreads();
    if (i < n) {
        int inc = x + sExc;
        off[i + 1] = inc;
        cur[i] = inc - v;
        if (i == 0) off[0] = 0;
    }
}

// -------- scatter + restore deg/partf zero-invariant for next call --------
__global__ void scatter_kernel(const int* __restrict__ src, const int* __restrict__ dst,
                               int* __restrict__ cur, int* __restrict__ adj, int ne) {
    int e = blockIdx.x * blockDim.x + threadIdx.x;
    if (e < ne) {
        int s = src[e], d = dst[e];
        int p = atomicAdd(&cur[s], 1);        adj[p] = d;
        int q = atomicAdd(&cur[NGn + d], 1);  adj[q] = s;
    }
    if (e < Mn) g_deg[e] = 0;          // deg consumed by scan; re-zero for next call
    if (e < 128) g_partf[e] = 0;       // lookback flags re-zero
}

// -------- warp-per-node gather-mean: 8-lane groups cover full rows (uint4) --------
__global__ __launch_bounds__(256) void gather_h(
    const uint4* __restrict__ xg4, const uint4* __restrict__ xd4,
    const int* __restrict__ off, const int* __restrict__ adj,
    uint4* __restrict__ outG, uint4* __restrict__ outD)
{
    int w = (blockIdx.x * blockDim.x + threadIdx.x) >> 5;
    if (w >= Mn) return;
    int lane = threadIdx.x & 31;
    int g = lane >> 3, l = lane & 7;
    int beg = off[w], end = off[w + 1];
    const uint4* __restrict__ x4 = (w < NGn) ? xd4 : xg4;

    float2 a0 = {0.f, 0.f}, a1 = {0.f, 0.f}, a2 = {0.f, 0.f}, a3 = {0.f, 0.f};
    int deg = end - beg;
    if (deg > 0) {
        int j = beg;
        for (; j + 8 <= end; j += 8) {
            int n0 = __ldg(&adj[j + g]);
            int n1 = __ldg(&adj[j + 4 + g]);
            uint4 v0 = __ldg(&x4[(size_t)n0 * 8 + l]);
            uint4 v1 = __ldg(&x4[(size_t)n1 * 8 + l]);
            acc_u4(a0, a1, a2, a3, v0);
            acc_u4(a0, a1, a2, a3, v1);
        }
        for (; j < end; j += 4) {
            int k = j + g;
            if (k < end) {
                int nn = __ldg(&adj[k]);
                uint4 v = __ldg(&x4[(size_t)nn * 8 + l]);
                acc_u4(a0, a1, a2, a3, v);
            }
        }
    }
    #pragma unroll
    for (int o = 8; o <= 16; o <<= 1) {
        a0.x += __shfl_xor_sync(0xFFFFFFFFu, a0.x, o);
        a0.y += __shfl_xor_sync(0xFFFFFFFFu, a0.y, o);
        a1.x += __shfl_xor_sync(0xFFFFFFFFu, a1.x, o);
        a1.y += __shfl_xor_sync(0xFFFFFFFFu, a1.y, o);
        a2.x += __shfl_xor_sync(0xFFFFFFFFu, a2.x, o);
        a2.y += __shfl_xor_sync(0xFFFFFFFFu, a2.y, o);
        a3.x += __shfl_xor_sync(0xFFFFFFFFu, a3.x, o);
        a3.y += __shfl_xor_sync(0xFFFFFFFFu, a3.y, o);
    }
    if (g == 0) {
        float inv = 1.0f / fmaxf((float)deg, 1.0f);
        uint4 o;
        o.x = packh2(a0.x * inv, a0.y * inv);
        o.y = packh2(a1.x * inv, a1.y * inv);
        o.z = packh2(a2.x * inv, a2.y * inv);
        o.w = packh2(a3.x * inv, a3.y * inv);
        if (w < NGn) outG[(size_t)w * 8 + l] = o;
        else         outD[(size_t)(w - NGn) * 8 + l] = o;
    }
}

// -------- persistent per-layer SAGE linear: smem-staged A + pre-packed fp16 B --------
#define LIN_GRID 592
__global__ __launch_bounds__(256) void sage_mma2(
    const uint4* __restrict__ mD4, const uint4* __restrict__ xD4,
    const uint2* __restrict__ wpD, const float* __restrict__ bDp,
    __half2* __restrict__ outDh, int nD,
    const uint4* __restrict__ mG4, const uint4* __restrict__ xG4,
    const uint2* __restrict__ wpG, const float* __restrict__ bGp,
    __half2* __restrict__ outGh, int nG,
    int relu)
{
    __shared__ uint2 sB[2048];
    __shared__ float sBias[64];
    __shared__ uint32_t sA[128][36];

    int nbD = (nD + 127) / 128;
    int nbG = (nG + 127) / 128;
    int split = (int)(((long long)LIN_GRID * nbD) / (nbD + nbG));
    if (split < 1) split = 1;
    bool isD = ((int)blockIdx.x < split);
    const uint4* mean4  = isD ? mD4 : mG4;
    const uint4* x4     = isD ? xD4 : xG4;
    const uint2* wp     = isD ? wpD : wpG;
    const float* bias   = isD ? bDp : bGp;
    __half2* out_h      = isD ? outDh : outGh;
    int n               = isD ? nD : nG;
    int nTiles          = isD ? nbD : nbG;
    int blk0            = isD ? blockIdx.x : (blockIdx.x - split);
    int nBlkSeg         = isD ? split : (LIN_GRID - split);

    int tid = threadIdx.x;

    for (int i = tid; i < 2048; i += 256) sB[i] = __ldg(&wp[i]);
    if (tid < 64) sBias[tid] = bias[tid];

    int warp = tid >> 5, lane = tid & 31;
    int t = lane & 3, g = lane >> 2;
    int la = warp * 16 + g, lb = la + 8;

    for (int blk = blk0; blk < nTiles; blk += nBlkSeg) {
        int tileBase = blk * 128;
        int ra = tileBase + la, rb = tileBase + lb;
        bool va = ra < n, vb = rb < n;

        float c_[8][4];

        __syncthreads();
        #pragma unroll
        for (int r4 = 0; r4 < 4; r4++) {
            int flat = tid + r4 * 256;
            int row = flat >> 3, c4 = flat & 7;
            int gr = tileBase + row;
            uint4 v = __ldg(&mean4[(size_t)(gr < n ? gr : 0) * 8 + c4]);
            *(uint4*)&sA[row][c4 * 4] = v;
        }
        __syncthreads();

        #pragma unroll
        for (int nt = 0; nt < 8; nt++) {
            float b0 = sBias[nt * 8 + 2 * t];
            float b1 = sBias[nt * 8 + 2 * t + 1];
            c_[nt][0] = b0; c_[nt][1] = b1; c_[nt][2] = b0; c_[nt][3] = b1;
        }

        #pragma unroll
        for (int kc = 0; kc < 4; kc++) {
            int b8 = kc * 8;
            uint32_t a0 = sA[la][b8 + t];
            uint32_t a1 = sA[lb][b8 + t];
            uint32_t a2 = sA[la][b8 + t + 4];
            uint32_t a3 = sA[lb][b8 + t + 4];
            #pragma unroll
            for (int nt = 0; nt < 8; nt++) {
                uint2 B = sB[kc * 256 + nt * 32 + lane];
                mma16(c_[nt], a0, a1, a2, a3, B.x, B.y);
            }
        }

        __syncthreads();
        #pragma unroll
        for (int r4 = 0; r4 < 4; r4++) {
            int flat = tid + r4 * 256;
            int row = flat >> 3, c4 = flat & 7;
            int gr = tileBase + row;
            uint4 v = __ldg(&x4[(size_t)(gr < n ? gr : 0) * 8 + c4]);
            *(uint4*)&sA[row][c4 * 4] = v;
        }
        __syncthreads();

        #pragma unroll
        for (int kc = 4; kc < 8; kc++) {
            int b8 = (kc & 3) * 8;
            uint32_t a0 = sA[la][b8 + t];
            uint32_t a1 = sA[lb][b8 + t];
            uint32_t a2 = sA[la][b8 + t + 4];
            uint32_t a3 = sA[lb][b8 + t + 4];
            #pragma unroll
            for (int nt = 0; nt < 8; nt++) {
                uint2 B = sB[kc * 256 + nt * 32 + lane];
                mma16(c_[nt], a0, a1, a2, a3, B.x, B.y);
            }
        }

        #pragma unroll
        for (int nt = 0; nt < 8; nt++) {
            float c0 = c_[nt][0], c1 = c_[nt][1], c2 = c_[nt][2], c3 = c_[nt][3];
            if (relu) {
                c0 = fmaxf(c0, 0.f); c1 = fmaxf(c1, 0.f);
                c2 = fmaxf(c2, 0.f); c3 = fmaxf(c3, 0.f);
            }
            if (va) out_h[(size_t)ra * 32 + nt * 4 + t] = __floats2half2_rn(c0, c1);
            if (vb) out_h[(size_t)rb * 32 + nt * 4 + t] = __floats2half2_rn(c2, c3);
        }
    }
}

// -------- label-edge dot product over fp16 rows, fp32 accumulate --------
__global__ __launch_bounds__(256) void dot_h(
    const __half2* __restrict__ hg2, const __half2* __restrict__ hd2,
    const int* __restrict__ ls, const int* __restrict__ ld,
    float* __restrict__ out, int nl)
{
    int t = blockIdx.x * blockDim.x + threadIdx.x;
    int e = t >> 3;
    if (e >= nl) return;
    int lane = t & 7;
    int a = ls[e];
    int b = ld[e];
    const uint4* pg = (const uint4*)(hg2 + (size_t)a * 32);
    const uint4* pd = (const uint4*)(hd2 + (size_t)b * 32);
    uint4 G = __ldg(&pg[lane]);
    uint4 D = __ldg(&pd[lane]);

    float acc = 0.f;
    {
        float2 g0 = __half22float2(*(__half2*)&G.x), d0 = __half22float2(*(__half2*)&D.x);
        float2 g1 = __half22float2(*(__half2*)&G.y), d1 = __half22float2(*(__half2*)&D.y);
        float2 g2 = __half22float2(*(__half2*)&G.z), d2 = __half22float2(*(__half2*)&D.z);
        float2 g3 = __half22float2(*(__half2*)&G.w), d3 = __half22float2(*(__half2*)&D.w);
        acc = g0.x * d0.x + g0.y * d0.y + g1.x * d1.x + g1.y * d1.y
            + g2.x * d2.x + g2.y * d2.y + g3.x * d3.x + g3.y * d3.y;
    }
    acc += __shfl_down_sync(0xFFFFFFFFu, acc, 4);
    acc += __shfl_down_sync(0xFFFFFFFFu, acc, 2);
    acc += __shfl_down_sync(0xFFFFFFFFu, acc, 1);
    if (lane == 0) out[e] = acc;
}

extern "C" void kernel_launch(void* const* d_in, const int* in_sizes, int n_in,
                              void* d_out, int out_size)
{
    const float* gene = nullptr;
    const float* dis  = nullptr;
    const float* w[8] = {};
    const float* b[4] = {};
    const int*   edge[2] = {};
    const int*   lab[2]  = {};
    int wi = 0, bi = 0, ei = 0, li = 0;
    int ne = 0, nl = 0;

    for (int i = 0; i < n_in; i++) {
        int sz = in_sizes[i];
        if (sz == NGn * H)          gene = (const float*)d_in[i];
        else if (sz == NDn * H)     dis  = (const float*)d_in[i];
        else if (sz == H * H)       { if (wi < 8) w[wi++] = (const float*)d_in[i]; }
        else if (sz == H)           { if (bi < 4) b[bi++] = (const float*)d_in[i]; }
        else if (sz == 1500000)     { if (ei < 2) { edge[ei++] = (const int*)d_in[i]; ne = sz; } }
        else if (sz == 500000)      { if (li < 2) { lab[li++]  = (const int*)d_in[i]; nl = sz; } }
    }

    int *off, *cur, *adj;
    __half2 *geneH, *disH, *hgH, *hdH, *mGH, *mDH;
    uint2 *wPack;
    cudaGetSymbolAddress((void**)&off,   g_off);
    cudaGetSymbolAddress((void**)&cur,   g_cur);
    cudaGetSymbolAddress((void**)&adj,   g_adj);
    cudaGetSymbolAddress((void**)&geneH, g_geneH);
    cudaGetSymbolAddress((void**)&disH,  g_disH);
    cudaGetSymbolAddress((void**)&hgH,   g_hgH);
    cudaGetSymbolAddress((void**)&hdH,   g_hdH);
    cudaGetSymbolAddress((void**)&mGH,   g_mGH);
    cudaGetSymbolAddress((void**)&mDH,   g_mDH);
    cudaGetSymbolAddress((void**)&wPack, g_wPack);

    int egrid = (ne + 255) / 256;
    int ggrid = (Mn * 32 + 255) / 256;
    int ph_grid = PREP_BLOCKS + egrid;

    // ---- fused prep+hist -> single-pass scan -> scatter (restores invariants) ----
    prep_hist<<<ph_grid, 256>>>(
        (const float2*)gene, geneH, (const float2*)dis, disH,
        w[0], w[1], w[2], w[3], w[4], w[5], w[6], w[7], wPack,
        edge[0], edge[1], ne);
    scan_fused<<<NBLK, 1024>>>(off, cur, Mn);
    scatter_kernel<<<egrid, 256>>>(edge[0], edge[1], cur, adj, ne);

    // ---- layer 1 ----
    gather_h<<<ggrid, 256>>>((const uint4*)geneH, (const uint4*)disH, off, adj,
                             (uint4*)mGH, (uint4*)mDH);
    sage_mma2<<<LIN_GRID, 256>>>(
        (const uint4*)mDH, (const uint4*)disH,  wPack + 0,    b[0], hdH, NDn,
        (const uint4*)mGH, (const uint4*)geneH, wPack + 2048, b[1], hgH, NGn, 1);

    // ---- layer 2 (fp16 outputs written in-place over hgH/hdH) ----
    gather_h<<<ggrid, 256>>>((const uint4*)hgH, (const uint4*)hdH, off, adj,
                             (uint4*)mGH, (uint4*)mDH);
    sage_mma2<<<LIN_GRID, 256>>>(
        (const uint4*)mDH, (const uint4*)hdH, wPack + 4096, b[2], hdH, NDn,
        (const uint4*)mGH, (const uint4*)hgH, wPack + 6144, b[3], hgH, NGn, 0);

    // ---- classifier (fp16 rows, fp32 accumulate) ----
    int dot_grid = (nl * 8 + 255) / 256;
    dot_h<<<dot_grid, 256>>>(hgH, hdH, lab[0], lab[1], (float*)d_out, nl);
}

// round 12
// speedup vs baseline: 1.2397x; 1.0204x over previous
#include <cuda_runtime.h>
#include <cuda_fp16.h>
#include <cstddef>
#include <cstdint>

#define H 64
#define NGn 100000
#define NDn 30000
#define Mn (NGn + NDn)
#define NEmax 1500000
#define SCAN_B 1024
#define NBLK ((Mn + SCAN_B - 1) / SCAN_B)   // 127

// -------- scratch (zero-initialized at module load; deg/partf invariant:
//          zero at every kernel_launch entry, restored by scatter each call) --------
__device__ int   g_deg [Mn];
__device__ int   g_partf[128];
__device__ int   g_off [Mn + 1];
__device__ int   g_cur [Mn];
__device__ __align__(16) int g_adj [2 * NEmax];
__device__ __half2 g_geneH[(size_t)NGn * 32];
__device__ __half2 g_disH [(size_t)NDn * 32];
__device__ __half2 g_hgH  [(size_t)NGn * 32];
__device__ __half2 g_hdH  [(size_t)NDn * 32];
__device__ __half2 g_mGH  [(size_t)NGn * 32];
__device__ __half2 g_mDH  [(size_t)NDn * 32];
__device__ uint2   g_wPack[4 * 2048];

// -------- helpers --------
__device__ __forceinline__ uint32_t packh2(float a, float b) {
    __half2 h = __floats2half2_rn(a, b);
    return *reinterpret_cast<uint32_t*>(&h);
}
__device__ __forceinline__ void mma16(float c[4],
                                      uint32_t a0, uint32_t a1, uint32_t a2, uint32_t a3,
                                      uint32_t b0, uint32_t b1) {
    asm volatile(
        "mma.sync.aligned.m16n8k16.row.col.f32.f16.f16.f32 "
        "{%0,%1,%2,%3},{%4,%5,%6,%7},{%8,%9},{%0,%1,%2,%3};"
        : "+f"(c[0]), "+f"(c[1]), "+f"(c[2]), "+f"(c[3])
        : "r"(a0), "r"(a1), "r"(a2), "r"(a3), "r"(b0), "r"(b1));
}
__device__ __forceinline__ void acc_u4(float2& a0, float2& a1, float2& a2, float2& a3,
                                       uint4 v) {
    const __half2* h = (const __half2*)&v;
    float2 f0 = __half22float2(h[0]);
    float2 f1 = __half22float2(h[1]);
    float2 f2 = __half22float2(h[2]);
    float2 f3 = __half22float2(h[3]);
    a0.x += f0.x; a0.y += f0.y;
    a1.x += f1.x; a1.y += f1.y;
    a2.x += f2.x; a2.y += f2.y;
    a3.x += f3.x; a3.y += f3.y;
}
// pairwise fp16 add of two rows, then fp32 accumulate (one extra 2^-11 rounding)
__device__ __forceinline__ void acc_u4_pair(float2& a0, float2& a1, float2& a2, float2& a3,
                                            uint4 v0, uint4 v1) {
    const __half2* h0 = (const __half2*)&v0;
    const __half2* h1 = (const __half2*)&v1;
    __half2 s0 = __hadd2(h0[0], h1[0]);
    __half2 s1 = __hadd2(h0[1], h1[1]);
    __half2 s2 = __hadd2(h0[2], h1[2]);
    __half2 s3 = __hadd2(h0[3], h1[3]);
    float2 f0 = __half22float2(s0);
    float2 f1 = __half22float2(s1);
    float2 f2 = __half22float2(s2);
    float2 f3 = __half22float2(s3);
    a0.x += f0.x; a0.y += f0.y;
    a1.x += f1.x; a1.y += f1.y;
    a2.x += f2.x; a2.y += f2.y;
    a3.x += f3.x; a3.y += f3.y;
}

// -------- fused prep (f2h + weight packing) + hist, block-range split --------
#define NG2   (NGn * 32)
#define ND2   (NDn * 32)
#define NWP   (4 * 2048)
#define PREP_ITEMS (NG2 + ND2 + NWP)
#define PREP_BLOCKS ((PREP_ITEMS + 255) / 256)
__global__ __launch_bounds__(256) void prep_hist(
    const float2* __restrict__ gene, __half2* __restrict__ geneH,
    const float2* __restrict__ dis,  __half2* __restrict__ disH,
    const float* __restrict__ w0, const float* __restrict__ w1,
    const float* __restrict__ w2, const float* __restrict__ w3,
    const float* __restrict__ w4, const float* __restrict__ w5,
    const float* __restrict__ w6, const float* __restrict__ w7,
    uint2* __restrict__ wPack,
    const int* __restrict__ src, const int* __restrict__ dst, int ne)
{
    int blk = blockIdx.x;
    if (blk < PREP_BLOCKS) {
        int i = blk * 256 + threadIdx.x;
        if (i < NG2) {
            float2 v = gene[i];
            geneH[i] = __floats2half2_rn(v.x, v.y);
        } else if (i < NG2 + ND2) {
            int j = i - NG2;
            float2 v = dis[j];
            disH[j] = __floats2half2_rn(v.x, v.y);
        } else if (i < PREP_ITEMS) {
            int p = i - (NG2 + ND2);
            int pi  = p >> 11;
            int rem = p & 2047;
            const float* wl;
            const float* wr;
            if      (pi == 0) { wl = w0; wr = w1; }
            else if (pi == 1) { wl = w2; wr = w3; }
            else if (pi == 2) { wl = w4; wr = w5; }
            else              { wl = w6; wr = w7; }
            int kc   = rem >> 8;
            int nt   = (rem >> 5) & 7;
            int lane = rem & 31;
            int t = lane & 3, g = lane >> 2;
            int c = nt * 8 + g;
            int k0 = kc * 16;
            int r0 = k0 + 2 * t, r2 = r0 + 8;
            float w00 = (r0 < 64)     ? wl[r0 * 64 + c]       : wr[(r0 - 64) * 64 + c];
            float w01 = (r0 + 1 < 64) ? wl[(r0 + 1) * 64 + c] : wr[(r0 - 63) * 64 + c];
            float w10 = (r2 < 64)     ? wl[r2 * 64 + c]       : wr[(r2 - 64) * 64 + c];
            float w11 = (r2 + 1 < 64) ? wl[(r2 + 1) * 64 + c] : wr[(r2 - 63) * 64 + c];
            wPack[p] = make_uint2(packh2(w00, w01), packh2(w10, w11));
        }
    } else {
        int e = (blk - PREP_BLOCKS) * 256 + threadIdx.x;
        if (e < ne) {
            atomicAdd(&g_deg[src[e]], 1);
            atomicAdd(&g_deg[NGn + dst[e]], 1);
        }
    }
}

// -------- single-pass scan with decoupled lookback (127 blocks, all resident) --------
__global__ __launch_bounds__(1024) void scan_fused(
    int* __restrict__ off, int* __restrict__ cur, int n)
{
    __shared__ int ws[32];
    __shared__ int sv[128];
    __shared__ int sExc;
    int bid = blockIdx.x;
    int tid = threadIdx.x;
    int i = bid * SCAN_B + tid;
    int v = (i < n) ? g_deg[i] : 0;
    int x = v;
    #pragma unroll
    for (int o = 1; o < 32; o <<= 1) {
        int y = __shfl_up_sync(0xFFFFFFFFu, x, o);
        if ((tid & 31) >= o) x += y;
    }
    if ((tid & 31) == 31) ws[tid >> 5] = x;
    __syncthreads();
    if (tid < 32) {
        int y = ws[tid];
        #pragma unroll
        for (int o = 1; o < 32; o <<= 1) {
            int z = __shfl_up_sync(0xFFFFFFFFu, y, o);
            if (tid >= o) y += z;
        }
        ws[tid] = y;
    }
    __syncthreads();
    if (tid >= 32) x += ws[(tid >> 5) - 1];
    if (tid == 1023) {
        atomicExch(&g_partf[bid], (x << 1) | 1);
    }
    if (tid < 128) sv[tid] = 0;
    __syncthreads();
    if (tid < bid) {
        int p;
        do { p = *(volatile int*)&g_partf[tid]; } while ((p & 1) == 0);
        sv[tid] = p >> 1;
    }
    __syncthreads();
    if (tid < 64) sv[tid] += sv[tid + 64];
    __syncthreads();
    if (tid < 32) {
        int s = sv[tid] + sv[tid + 32];
        #pragma unroll
        for (int o = 16; o; o >>= 1) s += __shfl_down_sync(0xFFFFFFFFu, s, o);
        if (tid == 0) sExc = s;
    }
    __syncthreads();
    if (i < n) {
        int inc = x + sExc;
        off[i + 1] = inc;
        cur[i] = inc - v;
        if (i == 0) off[0] = 0;
    }
}

// -------- scatter + restore deg/partf zero-invariant for next call --------
__global__ void scatter_kernel(const int* __restrict__ src, const int* __restrict__ dst,
                               int* __restrict__ cur, int* __restrict__ adj, int ne) {
    int e = blockIdx.x * blockDim.x + threadIdx.x;
    if (e < ne) {
        int s = src[e], d = dst[e];
        int p = atomicAdd(&cur[s], 1);        adj[p] = d;
        int q = atomicAdd(&cur[NGn + d], 1);  adj[q] = s;
    }
    if (e < Mn) g_deg[e] = 0;
    if (e < 128) g_partf[e] = 0;
}

// -------- warp-per-node gather-mean: 8-lane groups, pairwise fp16 pre-add --------
__global__ __launch_bounds__(256) void gather_h(
    const uint4* __restrict__ xg4, const uint4* __restrict__ xd4,
    const int* __restrict__ off, const int* __restrict__ adj,
    uint4* __restrict__ outG, uint4* __restrict__ outD)
{
    int w = (blockIdx.x * blockDim.x + threadIdx.x) >> 5;
    if (w >= Mn) return;
    int lane = threadIdx.x & 31;
    int g = lane >> 3, l = lane & 7;
    int beg = off[w], end = off[w + 1];
    const uint4* __restrict__ x4 = (w < NGn) ? xd4 : xg4;

    float2 a0 = {0.f, 0.f}, a1 = {0.f, 0.f}, a2 = {0.f, 0.f}, a3 = {0.f, 0.f};
    int deg = end - beg;
    if (deg > 0) {
        int j = beg;
        for (; j + 8 <= end; j += 8) {
            int n0 = __ldg(&adj[j + g]);
            int n1 = __ldg(&adj[j + 4 + g]);
            uint4 v0 = __ldg(&x4[(size_t)n0 * 8 + l]);
            uint4 v1 = __ldg(&x4[(size_t)n1 * 8 + l]);
            acc_u4_pair(a0, a1, a2, a3, v0, v1);
        }
        for (; j < end; j += 4) {
            int k = j + g;
            if (k < end) {
                int nn = __ldg(&adj[k]);
                uint4 v = __ldg(&x4[(size_t)nn * 8 + l]);
                acc_u4(a0, a1, a2, a3, v);
            }
        }
    }
    #pragma unroll
    for (int o = 8; o <= 16; o <<= 1) {
        a0.x += __shfl_xor_sync(0xFFFFFFFFu, a0.x, o);
        a0.y += __shfl_xor_sync(0xFFFFFFFFu, a0.y, o);
        a1.x += __shfl_xor_sync(0xFFFFFFFFu, a1.x, o);
        a1.y += __shfl_xor_sync(0xFFFFFFFFu, a1.y, o);
        a2.x += __shfl_xor_sync(0xFFFFFFFFu, a2.x, o);
        a2.y += __shfl_xor_sync(0xFFFFFFFFu, a2.y, o);
        a3.x += __shfl_xor_sync(0xFFFFFFFFu, a3.x, o);
        a3.y += __shfl_xor_sync(0xFFFFFFFFu, a3.y, o);
    }
    if (g == 0) {
        float inv = 1.0f / fmaxf((float)deg, 1.0f);
        uint4 o;
        o.x = packh2(a0.x * inv, a0.y * inv);
        o.y = packh2(a1.x * inv, a1.y * inv);
        o.z = packh2(a2.x * inv, a2.y * inv);
        o.w = packh2(a3.x * inv, a3.y * inv);
        if (w < NGn) outG[(size_t)w * 8 + l] = o;
        else         outD[(size_t)(w - NGn) * 8 + l] = o;
    }
}

// -------- persistent per-layer SAGE linear: smem-staged A + pre-packed fp16 B --------
#define LIN_GRID 592
__global__ __launch_bounds__(256) void sage_mma2(
    const uint4* __restrict__ mD4, const uint4* __restrict__ xD4,
    const uint2* __restrict__ wpD, const float* __restrict__ bDp,
    __half2* __restrict__ outDh, int nD,
    const uint4* __restrict__ mG4, const uint4* __restrict__ xG4,
    const uint2* __restrict__ wpG, const float* __restrict__ bGp,
    __half2* __restrict__ outGh, int nG,
    int relu)
{
    __shared__ uint2 sB[2048];
    __shared__ float sBias[64];
    __shared__ uint32_t sA[128][36];

    int nbD = (nD + 127) / 128;
    int nbG = (nG + 127) / 128;
    int split = (int)(((long long)LIN_GRID * nbD) / (nbD + nbG));
    if (split < 1) split = 1;
    bool isD = ((int)blockIdx.x < split);
    const uint4* mean4  = isD ? mD4 : mG4;
    const uint4* x4     = isD ? xD4 : xG4;
    const uint2* wp     = isD ? wpD : wpG;
    const float* bias   = isD ? bDp : bGp;
    __half2* out_h      = isD ? outDh : outGh;
    int n               = isD ? nD : nG;
    int nTiles          = isD ? nbD : nbG;
    int blk0            = isD ? blockIdx.x : (blockIdx.x - split);
    int nBlkSeg         = isD ? split : (LIN_GRID - split);

    int tid = threadIdx.x;

    for (int i = tid; i < 2048; i += 256) sB[i] = __ldg(&wp[i]);
    if (tid < 64) sBias[tid] = bias[tid];

    int warp = tid >> 5, lane = tid & 31;
    int t = lane & 3, g = lane >> 2;
    int la = warp * 16 + g, lb = la + 8;

    for (int blk = blk0; blk < nTiles; blk += nBlkSeg) {
        int tileBase = blk * 128;
        int ra = tileBase + la, rb = tileBase + lb;
        bool va = ra < n, vb = rb < n;

        float c_[8][4];

        __syncthreads();
        #pragma unroll
        for (int r4 = 0; r4 < 4; r4++) {
            int flat = tid + r4 * 256;
            int row = flat >> 3, c4 = flat & 7;
            int gr = tileBase + row;
            uint4 v = __ldg(&mean4[(size_t)(gr < n ? gr : 0) * 8 + c4]);
            *(uint4*)&sA[row][c4 * 4] = v;
        }
        __syncthreads();

        #pragma unroll
        for (int nt = 0; nt < 8; nt++) {
            float b0 = sBias[nt * 8 + 2 * t];
            float b1 = sBias[nt * 8 + 2 * t + 1];
            c_[nt][0] = b0; c_[nt][1] = b1; c_[nt][2] = b0; c_[nt][3] = b1;
        }

        #pragma unroll
        for (int kc = 0; kc < 4; kc++) {
            int b8 = kc * 8;
            uint32_t a0 = sA[la][b8 + t];
            uint32_t a1 = sA[lb][b8 + t];
            uint32_t a2 = sA[la][b8 + t + 4];
            uint32_t a3 = sA[lb][b8 + t + 4];
            #pragma unroll
            for (int nt = 0; nt < 8; nt++) {
                uint2 B = sB[kc * 256 + nt * 32 + lane];
                mma16(c_[nt], a0, a1, a2, a3, B.x, B.y);
            }
        }

        __syncthreads();
        #pragma unroll
        for (int r4 = 0; r4 < 4; r4++) {
            int flat = tid + r4 * 256;
            int row = flat >> 3, c4 = flat & 7;
            int gr = tileBase + row;
            uint4 v = __ldg(&x4[(size_t)(gr < n ? gr : 0) * 8 + c4]);
            *(uint4*)&sA[row][c4 * 4] = v;
        }
        __syncthreads();

        #pragma unroll
        for (int kc = 4; kc < 8; kc++) {
            int b8 = (kc & 3) * 8;
            uint32_t a0 = sA[la][b8 + t];
            uint32_t a1 = sA[lb][b8 + t];
            uint32_t a2 = sA[la][b8 + t + 4];
            uint32_t a3 = sA[lb][b8 + t + 4];
            #pragma unroll
            for (int nt = 0; nt < 8; nt++) {
                uint2 B = sB[kc * 256 + nt * 32 + lane];
                mma16(c_[nt], a0, a1, a2, a3, B.x, B.y);
            }
        }

        #pragma unroll
        for (int nt = 0; nt < 8; nt++) {
            float c0 = c_[nt][0], c1 = c_[nt][1], c2 = c_[nt][2], c3 = c_[nt][3];
            if (relu) {
                c0 = fmaxf(c0, 0.f); c1 = fmaxf(c1, 0.f);
                c2 = fmaxf(c2, 0.f); c3 = fmaxf(c3, 0.f);
            }
            if (va) out_h[(size_t)ra * 32 + nt * 4 + t] = __floats2half2_rn(c0, c1);
            if (vb) out_h[(size_t)rb * 32 + nt * 4 + t] = __floats2half2_rn(c2, c3);
        }
    }
}

// -------- label-edge dot product over fp16 rows, fp32 accumulate --------
__global__ __launch_bounds__(256) void dot_h(
    const __half2* __restrict__ hg2, const __half2* __restrict__ hd2,
    const int* __restrict__ ls, const int* __restrict__ ld,
    float* __restrict__ out, int nl)
{
    int t = blockIdx.x * blockDim.x + threadIdx.x;
    int e = t >> 3;
    if (e >= nl) return;
    int lane = t & 7;
    int a = ls[e];
    int b = ld[e];
    const uint4* pg = (const uint4*)(hg2 + (size_t)a * 32);
    const uint4* pd = (const uint4*)(hd2 + (size_t)b * 32);
    uint4 G = __ldg(&pg[lane]);
    uint4 D = __ldg(&pd[lane]);

    float acc = 0.f;
    {
        float2 g0 = __half22float2(*(__half2*)&G.x), d0 = __half22float2(*(__half2*)&D.x);
        float2 g1 = __half22float2(*(__half2*)&G.y), d1 = __half22float2(*(__half2*)&D.y);
        float2 g2 = __half22float2(*(__half2*)&G.z), d2 = __half22float2(*(__half2*)&D.z);
        float2 g3 = __half22float2(*(__half2*)&G.w), d3 = __half22float2(*(__half2*)&D.w);
        acc = g0.x * d0.x + g0.y * d0.y + g1.x * d1.x + g1.y * d1.y
            + g2.x * d2.x + g2.y * d2.y + g3.x * d3.x + g3.y * d3.y;
    }
    acc += __shfl_down_sync(0xFFFFFFFFu, acc, 4);
    acc += __shfl_down_sync(0xFFFFFFFFu, acc, 2);
    acc += __shfl_down_sync(0xFFFFFFFFu, acc, 1);
    if (lane == 0) out[e] = acc;
}

extern "C" void kernel_launch(void* const* d_in, const int* in_sizes, int n_in,
                              void* d_out, int out_size)
{
    const float* gene = nullptr;
    const float* dis  = nullptr;
    const float* w[8] = {};
    const float* b[4] = {};
    const int*   edge[2] = {};
    const int*   lab[2]  = {};
    int wi = 0, bi = 0, ei = 0, li = 0;
    int ne = 0, nl = 0;

    for (int i = 0; i < n_in; i++) {
        int sz = in_sizes[i];
        if (sz == NGn * H)          gene = (const float*)d_in[i];
        else if (sz == NDn * H)     dis  = (const float*)d_in[i];
        else if (sz == H * H)       { if (wi < 8) w[wi++] = (const float*)d_in[i]; }
        else if (sz == H)           { if (bi < 4) b[bi++] = (const float*)d_in[i]; }
        else if (sz == 1500000)     { if (ei < 2) { edge[ei++] = (const int*)d_in[i]; ne = sz; } }
        else if (sz == 500000)      { if (li < 2) { lab[li++]  = (const int*)d_in[i]; nl = sz; } }
    }

    int *off, *cur, *adj;
    __half2 *geneH, *disH, *hgH, *hdH, *mGH, *mDH;
    uint2 *wPack;
    cudaGetSymbolAddress((void**)&off,   g_off);
    cudaGetSymbolAddress((void**)&cur,   g_cur);
    cudaGetSymbolAddress((void**)&adj,   g_adj);
    cudaGetSymbolAddress((void**)&geneH, g_geneH);
    cudaGetSymbolAddress((void**)&disH,  g_disH);
    cudaGetSymbolAddress((void**)&hgH,   g_hgH);
    cudaGetSymbolAddress((void**)&hdH,   g_hdH);
    cudaGetSymbolAddress((void**)&mGH,   g_mGH);
    cudaGetSymbolAddress((void**)&mDH,   g_mDH);
    cudaGetSymbolAddress((void**)&wPack, g_wPack);

    int egrid = (ne + 255) / 256;
    int ggrid = (Mn * 32 + 255) / 256;
    int ph_grid = PREP_BLOCKS + egrid;

    // ---- fused prep+hist -> single-pass scan -> scatter (restores invariants) ----
    prep_hist<<<ph_grid, 256>>>(
        (const float2*)gene, geneH, (const float2*)dis, disH,
        w[0], w[1], w[2], w[3], w[4], w[5], w[6], w[7], wPack,
        edge[0], edge[1], ne);
    scan_fused<<<NBLK, 1024>>>(off, cur, Mn);
    scatter_kernel<<<egrid, 256>>>(edge[0], edge[1], cur, adj, ne);

    // ---- layer 1 ----
    gather_h<<<ggrid, 256>>>((const uint4*)geneH, (const uint4*)disH, off, adj,
                             (uint4*)mGH, (uint4*)mDH);
    sage_mma2<<<LIN_GRID, 256>>>(
        (const uint4*)mDH, (const uint4*)disH,  wPack + 0,    b[0], hdH, NDn,
        (const uint4*)mGH, (const uint4*)geneH, wPack + 2048, b[1], hgH, NGn, 1);

    // ---- layer 2 (fp16 outputs written in-place over hgH/hdH) ----
    gather_h<<<ggrid, 256>>>((const uint4*)hgH, (const uint4*)hdH, off, adj,
                             (uint4*)mGH, (uint4*)mDH);
    sage_mma2<<<LIN_GRID, 256>>>(
        (const uint4*)mDH, (const uint4*)hdH, wPack + 4096, b[2], hdH, NDn,
        (const uint4*)mGH, (const uint4*)hgH, wPack + 6144, b[3], hgH, NGn, 0);

    // ---- classifier (fp16 rows, fp32 accumulate) ----
    int dot_grid = (nl * 8 + 255) / 256;
    dot_h<<<dot_grid, 256>>>(hgH, hdH, lab[0], lab[1], (float*)d_out, nl);
}

// round 13
// speedup vs baseline: 1.2430x; 1.0027x over previous
#include <cuda_runtime.h>
#include <cuda_fp16.h>
#include <cstddef>
#include <cstdint>

#define H 64
#define NGn 100000
#define NDn 30000
#define Mn (NGn + NDn)
#define NEmax 1500000
#define SCAN_B 1024
#define NBLK ((Mn + SCAN_B - 1) / SCAN_B)   // 127

// -------- scratch (zero-initialized at module load; deg/partf invariant:
//          zero at every kernel_launch entry, restored by scatter each call) --------
__device__ int   g_deg [Mn];
__device__ int   g_partf[128];
__device__ int   g_off [Mn + 1];
__device__ int   g_cur [Mn];
__device__ __align__(16) int g_adj [2 * NEmax];   // stores BYTE offsets (idx << 7)
__device__ __half2 g_geneH[(size_t)NGn * 32];
__device__ __half2 g_disH [(size_t)NDn * 32];
__device__ __half2 g_hgH  [(size_t)NGn * 32];
__device__ __half2 g_hdH  [(size_t)NDn * 32];
__device__ __half2 g_mGH  [(size_t)NGn * 32];
__device__ __half2 g_mDH  [(size_t)NDn * 32];
__device__ uint2   g_wPack[4 * 2048];

// -------- helpers --------
__device__ __forceinline__ uint32_t packh2(float a, float b) {
    __half2 h = __floats2half2_rn(a, b);
    return *reinterpret_cast<uint32_t*>(&h);
}
__device__ __forceinline__ void mma16(float c[4],
                                      uint32_t a0, uint32_t a1, uint32_t a2, uint32_t a3,
                                      uint32_t b0, uint32_t b1) {
    asm volatile(
        "mma.sync.aligned.m16n8k16.row.col.f32.f16.f16.f32 "
        "{%0,%1,%2,%3},{%4,%5,%6,%7},{%8,%9},{%0,%1,%2,%3};"
        : "+f"(c[0]), "+f"(c[1]), "+f"(c[2]), "+f"(c[3])
        : "r"(a0), "r"(a1), "r"(a2), "r"(a3), "r"(b0), "r"(b1));
}
// packed fp32x2 accumulate of one half2 (cvt + add.rn.f32x2)
__device__ __forceinline__ void accx2(unsigned long long& acc, __half2 h) {
    float2 f = __half22float2(h);
    unsigned long long v;
    asm("mov.b64 %0, {%1, %2};" : "=l"(v) : "f"(f.x), "f"(f.y));
    asm("add.rn.f32x2 %0, %0, %1;" : "+l"(acc) : "l"(v));
}
__device__ __forceinline__ void acc_u4_x2(unsigned long long* aa, uint4 v) {
    const __half2* h = (const __half2*)&v;
    accx2(aa[0], h[0]);
    accx2(aa[1], h[1]);
    accx2(aa[2], h[2]);
    accx2(aa[3], h[3]);
}
// pairwise fp16 add of two rows, then packed fp32 accumulate
__device__ __forceinline__ void acc_u4_pair_x2(unsigned long long* aa, uint4 v0, uint4 v1) {
    const __half2* h0 = (const __half2*)&v0;
    const __half2* h1 = (const __half2*)&v1;
    accx2(aa[0], __hadd2(h0[0], h1[0]));
    accx2(aa[1], __hadd2(h0[1], h1[1]));
    accx2(aa[2], __hadd2(h0[2], h1[2]));
    accx2(aa[3], __hadd2(h0[3], h1[3]));
}

// -------- fused prep (f2h + weight packing) + hist, block-range split --------
#define NG2   (NGn * 32)
#define ND2   (NDn * 32)
#define NWP   (4 * 2048)
#define PREP_ITEMS (NG2 + ND2 + NWP)
#define PREP_BLOCKS ((PREP_ITEMS + 255) / 256)
__global__ __launch_bounds__(256) void prep_hist(
    const float2* __restrict__ gene, __half2* __restrict__ geneH,
    const float2* __restrict__ dis,  __half2* __restrict__ disH,
    const float* __restrict__ w0, const float* __restrict__ w1,
    const float* __restrict__ w2, const float* __restrict__ w3,
    const float* __restrict__ w4, const float* __restrict__ w5,
    const float* __restrict__ w6, const float* __restrict__ w7,
    uint2* __restrict__ wPack,
    const int* __restrict__ src, const int* __restrict__ dst, int ne)
{
    int blk = blockIdx.x;
    if (blk < PREP_BLOCKS) {
        int i = blk * 256 + threadIdx.x;
        if (i < NG2) {
            float2 v = gene[i];
            geneH[i] = __floats2half2_rn(v.x, v.y);
        } else if (i < NG2 + ND2) {
            int j = i - NG2;
            float2 v = dis[j];
            disH[j] = __floats2half2_rn(v.x, v.y);
        } else if (i < PREP_ITEMS) {
            int p = i - (NG2 + ND2);
            int pi  = p >> 11;
            int rem = p & 2047;
            const float* wl;
            const float* wr;
            if      (pi == 0) { wl = w0; wr = w1; }
            else if (pi == 1) { wl = w2; wr = w3; }
            else if (pi == 2) { wl = w4; wr = w5; }
            else              { wl = w6; wr = w7; }
            int kc   = rem >> 8;
            int nt   = (rem >> 5) & 7;
            int lane = rem & 31;
            int t = lane & 3, g = lane >> 2;
            int c = nt * 8 + g;
            int k0 = kc * 16;
            int r0 = k0 + 2 * t, r2 = r0 + 8;
            float w00 = (r0 < 64)     ? wl[r0 * 64 + c]       : wr[(r0 - 64) * 64 + c];
            float w01 = (r0 + 1 < 64) ? wl[(r0 + 1) * 64 + c] : wr[(r0 - 63) * 64 + c];
            float w10 = (r2 < 64)     ? wl[r2 * 64 + c]       : wr[(r2 - 64) * 64 + c];
            float w11 = (r2 + 1 < 64) ? wl[(r2 + 1) * 64 + c] : wr[(r2 - 63) * 64 + c];
            wPack[p] = make_uint2(packh2(w00, w01), packh2(w10, w11));
        }
    } else {
        int e = (blk - PREP_BLOCKS) * 256 + threadIdx.x;
        if (e < ne) {
            atomicAdd(&g_deg[src[e]], 1);
            atomicAdd(&g_deg[NGn + dst[e]], 1);
        }
    }
}

// -------- single-pass scan with decoupled lookback (127 blocks, all resident) --------
__global__ __launch_bounds__(1024) void scan_fused(
    int* __restrict__ off, int* __restrict__ cur, int n)
{
    __shared__ int ws[32];
    __shared__ int sv[128];
    __shared__ int sExc;
    int bid = blockIdx.x;
    int tid = threadIdx.x;
    int i = bid * SCAN_B + tid;
    int v = (i < n) ? g_deg[i] : 0;
    int x = v;
    #pragma unroll
    for (int o = 1; o < 32; o <<= 1) {
        int y = __shfl_up_sync(0xFFFFFFFFu, x, o);
        if ((tid & 31) >= o) x += y;
    }
    if ((tid & 31) == 31) ws[tid >> 5] = x;
    __syncthreads();
    if (tid < 32) {
        int y = ws[tid];
        #pragma unroll
        for (int o = 1; o < 32; o <<= 1) {
            int z = __shfl_up_sync(0xFFFFFFFFu, y, o);
            if (tid >= o) y += z;
        }
        ws[tid] = y;
    }
    __syncthreads();
    if (tid >= 32) x += ws[(tid >> 5) - 1];
    if (tid == 1023) {
        atomicExch(&g_partf[bid], (x << 1) | 1);
    }
    if (tid < 128) sv[tid] = 0;
    __syncthreads();
    if (tid < bid) {
        int p;
        do { p = *(volatile int*)&g_partf[tid]; } while ((p & 1) == 0);
        sv[tid] = p >> 1;
    }
    __syncthreads();
    if (tid < 64) sv[tid] += sv[tid + 64];
    __syncthreads();
    if (tid < 32) {
        int s = sv[tid] + sv[tid + 32];
        #pragma unroll
        for (int o = 16; o; o >>= 1) s += __shfl_down_sync(0xFFFFFFFFu, s, o);
        if (tid == 0) sExc = s;
    }
    __syncthreads();
    if (i < n) {
        int inc = x + sExc;
        off[i + 1] = inc;
        cur[i] = inc - v;
        if (i == 0) off[0] = 0;
    }
}

// -------- scatter (stores PRE-SCALED byte offsets) + restore invariants --------
__global__ void scatter_kernel(const int* __restrict__ src, const int* __restrict__ dst,
                               int* __restrict__ cur, int* __restrict__ adj, int ne) {
    int e = blockIdx.x * blockDim.x + threadIdx.x;
    if (e < ne) {
        int s = src[e], d = dst[e];
        int p = atomicAdd(&cur[s], 1);        adj[p] = d << 7;   // byte offset of 128B row
        int q = atomicAdd(&cur[NGn + d], 1);  adj[q] = s << 7;
    }
    if (e < Mn) g_deg[e] = 0;
    if (e < 128) g_partf[e] = 0;
}

// -------- warp-per-node gather-mean: byte-offset adj, f32x2 accumulate --------
__global__ __launch_bounds__(256) void gather_h(
    const char* __restrict__ xgB, const char* __restrict__ xdB,
    const int* __restrict__ off, const int* __restrict__ adj,
    uint4* __restrict__ outG, uint4* __restrict__ outD)
{
    int w = (blockIdx.x * blockDim.x + threadIdx.x) >> 5;
    if (w >= Mn) return;
    int lane = threadIdx.x & 31;
    int g = lane >> 3, l = lane & 7;
    int beg = off[w], end = off[w + 1];
    // hoist the lane's 16B slice into the base pointer: addr = xb + byte_off
    const char* __restrict__ xb = ((w < NGn) ? xdB : xgB) + (l << 4);

    unsigned long long aa[4];
    {
        unsigned long long z;
        asm("mov.b64 %0, {%1, %2};" : "=l"(z) : "f"(0.0f), "f"(0.0f));
        aa[0] = z; aa[1] = z; aa[2] = z; aa[3] = z;
    }
    int deg = end - beg;
    if (deg > 0) {
        int j = beg;
        for (; j + 8 <= end; j += 8) {
            int o0 = __ldg(&adj[j + g]);
            int o1 = __ldg(&adj[j + 4 + g]);
            uint4 v0 = *(const uint4*)(xb + o0);
            uint4 v1 = *(const uint4*)(xb + o1);
            acc_u4_pair_x2(aa, v0, v1);
        }
        for (; j < end; j += 4) {
            int k = j + g;
            if (k < end) {
                int oo = __ldg(&adj[k]);
                uint4 v = *(const uint4*)(xb + oo);
                acc_u4_x2(aa, v);
            }
        }
    }
    // unpack to 8 floats, butterfly-reduce the 4 group partials
    float2 a0, a1, a2, a3;
    asm("mov.b64 {%0, %1}, %2;" : "=f"(a0.x), "=f"(a0.y) : "l"(aa[0]));
    asm("mov.b64 {%0, %1}, %2;" : "=f"(a1.x), "=f"(a1.y) : "l"(aa[1]));
    asm("mov.b64 {%0, %1}, %2;" : "=f"(a2.x), "=f"(a2.y) : "l"(aa[2]));
    asm("mov.b64 {%0, %1}, %2;" : "=f"(a3.x), "=f"(a3.y) : "l"(aa[3]));
    #pragma unroll
    for (int o = 8; o <= 16; o <<= 1) {
        a0.x += __shfl_xor_sync(0xFFFFFFFFu, a0.x, o);
        a0.y += __shfl_xor_sync(0xFFFFFFFFu, a0.y, o);
        a1.x += __shfl_xor_sync(0xFFFFFFFFu, a1.x, o);
        a1.y += __shfl_xor_sync(0xFFFFFFFFu, a1.y, o);
        a2.x += __shfl_xor_sync(0xFFFFFFFFu, a2.x, o);
        a2.y += __shfl_xor_sync(0xFFFFFFFFu, a2.y, o);
        a3.x += __shfl_xor_sync(0xFFFFFFFFu, a3.x, o);
        a3.y += __shfl_xor_sync(0xFFFFFFFFu, a3.y, o);
    }
    if (g == 0) {
        float inv = 1.0f / fmaxf((float)deg, 1.0f);
        uint4 o;
        o.x = packh2(a0.x * inv, a0.y * inv);
        o.y = packh2(a1.x * inv, a1.y * inv);
        o.z = packh2(a2.x * inv, a2.y * inv);
        o.w = packh2(a3.x * inv, a3.y * inv);
        if (w < NGn) outG[(size_t)w * 8 + l] = o;
        else         outD[(size_t)(w - NGn) * 8 + l] = o;
    }
}

// -------- persistent per-layer SAGE linear: smem-staged A + pre-packed fp16 B --------
#define LIN_GRID 592
__global__ __launch_bounds__(256) void sage_mma2(
    const uint4* __restrict__ mD4, const uint4* __restrict__ xD4,
    const uint2* __restrict__ wpD, const float* __restrict__ bDp,
    __half2* __restrict__ outDh, int nD,
    const uint4* __restrict__ mG4, const uint4* __restrict__ xG4,
    const uint2* __restrict__ wpG, const float* __restrict__ bGp,
    __half2* __restrict__ outGh, int nG,
    int relu)
{
    __shared__ uint2 sB[2048];
    __shared__ float sBias[64];
    __shared__ uint32_t sA[128][36];

    int nbD = (nD + 127) / 128;
    int nbG = (nG + 127) / 128;
    int split = (int)(((long long)LIN_GRID * nbD) / (nbD + nbG));
    if (split < 1) split = 1;
    bool isD = ((int)blockIdx.x < split);
    const uint4* mean4  = isD ? mD4 : mG4;
    const uint4* x4     = isD ? xD4 : xG4;
    const uint2* wp     = isD ? wpD : wpG;
    const float* bias   = isD ? bDp : bGp;
    __half2* out_h      = isD ? outDh : outGh;
    int n               = isD ? nD : nG;
    int nTiles          = isD ? nbD : nbG;
    int blk0            = isD ? blockIdx.x : (blockIdx.x - split);
    int nBlkSeg         = isD ? split : (LIN_GRID - split);

    int tid = threadIdx.x;

    for (int i = tid; i < 2048; i += 256) sB[i] = __ldg(&wp[i]);
    if (tid < 64) sBias[tid] = bias[tid];

    int warp = tid >> 5, lane = tid & 31;
    int t = lane & 3, g = lane >> 2;
    int la = warp * 16 + g, lb = la + 8;

    for (int blk = blk0; blk < nTiles; blk += nBlkSeg) {
        int tileBase = blk * 128;
        int ra = tileBase + la, rb = tileBase + lb;
        bool va = ra < n, vb = rb < n;

        float c_[8][4];

        __syncthreads();
        #pragma unroll
        for (int r4 = 0; r4 < 4; r4++) {
            int flat = tid + r4 * 256;
            int row = flat >> 3, c4 = flat & 7;
            int gr = tileBase + row;
            uint4 v = __ldg(&mean4[(size_t)(gr < n ? gr : 0) * 8 + c4]);
            *(uint4*)&sA[row][c4 * 4] = v;
        }
        __syncthreads();

        #pragma unroll
        for (int nt = 0; nt < 8; nt++) {
            float b0 = sBias[nt * 8 + 2 * t];
            float b1 = sBias[nt * 8 + 2 * t + 1];
            c_[nt][0] = b0; c_[nt][1] = b1; c_[nt][2] = b0; c_[nt][3] = b1;
        }

        #pragma unroll
        for (int kc = 0; kc < 4; kc++) {
            int b8 = kc * 8;
            uint32_t a0 = sA[la][b8 + t];
            uint32_t a1 = sA[lb][b8 + t];
            uint32_t a2 = sA[la][b8 + t + 4];
            uint32_t a3 = sA[lb][b8 + t + 4];
            #pragma unroll
            for (int nt = 0; nt < 8; nt++) {
                uint2 B = sB[kc * 256 + nt * 32 + lane];
                mma16(c_[nt], a0, a1, a2, a3, B.x, B.y);
            }
        }

        __syncthreads();
        #pragma unroll
        for (int r4 = 0; r4 < 4; r4++) {
            int flat = tid + r4 * 256;
            int row = flat >> 3, c4 = flat & 7;
            int gr = tileBase + row;
            uint4 v = __ldg(&x4[(size_t)(gr < n ? gr : 0) * 8 + c4]);
            *(uint4*)&sA[row][c4 * 4] = v;
        }
        __syncthreads();

        #pragma unroll
        for (int kc = 4; kc < 8; kc++) {
            int b8 = (kc & 3) * 8;
            uint32_t a0 = sA[la][b8 + t];
            uint32_t a1 = sA[lb][b8 + t];
            uint32_t a2 = sA[la][b8 + t + 4];
            uint32_t a3 = sA[lb][b8 + t + 4];
            #pragma unroll
            for (int nt = 0; nt < 8; nt++) {
                uint2 B = sB[kc * 256 + nt * 32 + lane];
                mma16(c_[nt], a0, a1, a2, a3, B.x, B.y);
            }
        }

        #pragma unroll
        for (int nt = 0; nt < 8; nt++) {
            float c0 = c_[nt][0], c1 = c_[nt][1], c2 = c_[nt][2], c3 = c_[nt][3];
            if (relu) {
                c0 = fmaxf(c0, 0.f); c1 = fmaxf(c1, 0.f);
                c2 = fmaxf(c2, 0.f); c3 = fmaxf(c3, 0.f);
            }
            if (va) out_h[(size_t)ra * 32 + nt * 4 + t] = __floats2half2_rn(c0, c1);
            if (vb) out_h[(size_t)rb * 32 + nt * 4 + t] = __floats2half2_rn(c2, c3);
        }
    }
}

// -------- label-edge dot product over fp16 rows, fp32 accumulate --------
__global__ __launch_bounds__(256) void dot_h(
    const __half2* __restrict__ hg2, const __half2* __restrict__ hd2,
    const int* __restrict__ ls, const int* __restrict__ ld,
    float* __restrict__ out, int nl)
{
    int t = blockIdx.x * blockDim.x + threadIdx.x;
    int e = t >> 3;
    if (e >= nl) return;
    int lane = t & 7;
    int a = ls[e];
    int b = ld[e];
    const uint4* pg = (const uint4*)(hg2 + (size_t)a * 32);
    const uint4* pd = (const uint4*)(hd2 + (size_t)b * 32);
    uint4 G = __ldg(&pg[lane]);
    uint4 D = __ldg(&pd[lane]);

    float acc = 0.f;
    {
        float2 g0 = __half22float2(*(__half2*)&G.x), d0 = __half22float2(*(__half2*)&D.x);
        float2 g1 = __half22float2(*(__half2*)&G.y), d1 = __half22float2(*(__half2*)&D.y);
        float2 g2 = __half22float2(*(__half2*)&G.z), d2 = __half22float2(*(__half2*)&D.z);
        float2 g3 = __half22float2(*(__half2*)&G.w), d3 = __half22float2(*(__half2*)&D.w);
        acc = g0.x * d0.x + g0.y * d0.y + g1.x * d1.x + g1.y * d1.y
            + g2.x * d2.x + g2.y * d2.y + g3.x * d3.x + g3.y * d3.y;
    }
    acc += __shfl_down_sync(0xFFFFFFFFu, acc, 4);
    acc += __shfl_down_sync(0xFFFFFFFFu, acc, 2);
    acc += __shfl_down_sync(0xFFFFFFFFu, acc, 1);
    if (lane == 0) out[e] = acc;
}

extern "C" void kernel_launch(void* const* d_in, const int* in_sizes, int n_in,
                              void* d_out, int out_size)
{
    const float* gene = nullptr;
    const float* dis  = nullptr;
    const float* w[8] = {};
    const float* b[4] = {};
    const int*   edge[2] = {};
    const int*   lab[2]  = {};
    int wi = 0, bi = 0, ei = 0, li = 0;
    int ne = 0, nl = 0;

    for (int i = 0; i < n_in; i++) {
        int sz = in_sizes[i];
        if (sz == NGn * H)          gene = (const float*)d_in[i];
        else if (sz == NDn * H)     dis  = (const float*)d_in[i];
        else if (sz == H * H)       { if (wi < 8) w[wi++] = (const float*)d_in[i]; }
        else if (sz == H)           { if (bi < 4) b[bi++] = (const float*)d_in[i]; }
        else if (sz == 1500000)     { if (ei < 2) { edge[ei++] = (const int*)d_in[i]; ne = sz; } }
        else if (sz == 500000)      { if (li < 2) { lab[li++]  = (const int*)d_in[i]; nl = sz; } }
    }

    int *off, *cur, *adj;
    __half2 *geneH, *disH, *hgH, *hdH, *mGH, *mDH;
    uint2 *wPack;
    cudaGetSymbolAddress((void**)&off,   g_off);
    cudaGetSymbolAddress((void**)&cur,   g_cur);
    cudaGetSymbolAddress((void**)&adj,   g_adj);
    cudaGetSymbolAddress((void**)&geneH, g_geneH);
    cudaGetSymbolAddress((void**)&disH,  g_disH);
    cudaGetSymbolAddress((void**)&hgH,   g_hgH);
    cudaGetSymbolAddress((void**)&hdH,   g_hdH);
    cudaGetSymbolAddress((void**)&mGH,   g_mGH);
    cudaGetSymbolAddress((void**)&mDH,   g_mDH);
    cudaGetSymbolAddress((void**)&wPack, g_wPack);

    int egrid = (ne + 255) / 256;
    int ggrid = (Mn * 32 + 255) / 256;
    int ph_grid = PREP_BLOCKS + egrid;

    // ---- fused prep+hist -> single-pass scan -> scatter (restores invariants) ----
    prep_hist<<<ph_grid, 256>>>(
        (const float2*)gene, geneH, (const float2*)dis, disH,
        w[0], w[1], w[2], w[3], w[4], w[5], w[6], w[7], wPack,
        edge[0], edge[1], ne);
    scan_fused<<<NBLK, 1024>>>(off, cur, Mn);
    scatter_kernel<<<egrid, 256>>>(edge[0], edge[1], cur, adj, ne);

    // ---- layer 1 ----
    gather_h<<<ggrid, 256>>>((const char*)geneH, (const char*)disH, off, adj,
                             (uint4*)mGH, (uint4*)mDH);
    sage_mma2<<<LIN_GRID, 256>>>(
        (const uint4*)mDH, (const uint4*)disH,  wPack + 0,    b[0], hdH, NDn,
        (const uint4*)mGH, (const uint4*)geneH, wPack + 2048, b[1], hgH, NGn, 1);

    // ---- layer 2 (fp16 outputs written in-place over hgH/hdH) ----
    gather_h<<<ggrid, 256>>>((const char*)hgH, (const char*)hdH, off, adj,
                             (uint4*)mGH, (uint4*)mDH);
    sage_mma2<<<LIN_GRID, 256>>>(
        (const uint4*)mDH, (const uint4*)hdH, wPack + 4096, b[2], hdH, NDn,
        (const uint4*)mGH, (const uint4*)hgH, wPack + 6144, b[3], hgH, NGn, 0);

    // ---- classifier (fp16 rows, fp32 accumulate) ----
    int dot_grid = (nl * 8 + 255) / 256;
    dot_h<<<dot_grid, 256>>>(hgH, hdH, lab[0], lab[1], (float*)d_out, nl);
}

// round 14
// speedup vs baseline: 1.3137x; 1.0569x over previous
#include <cuda_runtime.h>
#include <cuda_fp16.h>
#include <cstddef>
#include <cstdint>

#define H 64
#define NGn 100000
#define NDn 30000
#define Mn (NGn + NDn)
#define NEmax 1500000
#define SCAN_B 1024
#define NBLK ((Mn + SCAN_B - 1) / SCAN_B)   // 127

// -------- scratch (zero-initialized at module load).
// Invariant: g_deg/g_partf are zero at every kernel_launch entry; the LAST
// kernel (dot_h) restores this each call (g_deg is needed by the gathers). ----
__device__ int   g_deg [Mn];
__device__ int   g_partf[128];
__device__ int   g_off [Mn + 1];
__device__ int   g_cur [Mn];
__device__ __align__(16) int g_adj [2 * NEmax + 4 * Mn];  // byte offsets; padded to 4/node
// feature tables carry ONE extra all-zero sentinel row (never written)
__device__ __half2 g_geneH[(size_t)(NGn + 1) * 32];
__device__ __half2 g_disH [(size_t)(NDn + 1) * 32];
__device__ __half2 g_hgH  [(size_t)(NGn + 1) * 32];
__device__ __half2 g_hdH  [(size_t)(NDn + 1) * 32];
__device__ __half2 g_mGH  [(size_t)NGn * 32];
__device__ __half2 g_mDH  [(size_t)NDn * 32];
__device__ uint2   g_wPack[4 * 2048];

// -------- helpers --------
__device__ __forceinline__ uint32_t packh2(float a, float b) {
    __half2 h = __floats2half2_rn(a, b);
    return *reinterpret_cast<uint32_t*>(&h);
}
__device__ __forceinline__ void mma16(float c[4],
                                      uint32_t a0, uint32_t a1, uint32_t a2, uint32_t a3,
                                      uint32_t b0, uint32_t b1) {
    asm volatile(
        "mma.sync.aligned.m16n8k16.row.col.f32.f16.f16.f32 "
        "{%0,%1,%2,%3},{%4,%5,%6,%7},{%8,%9},{%0,%1,%2,%3};"
        : "+f"(c[0]), "+f"(c[1]), "+f"(c[2]), "+f"(c[3])
        : "r"(a0), "r"(a1), "r"(a2), "r"(a3), "r"(b0), "r"(b1));
}
__device__ __forceinline__ void accx2(unsigned long long& acc, __half2 h) {
    float2 f = __half22float2(h);
    unsigned long long v;
    asm("mov.b64 %0, {%1, %2};" : "=l"(v) : "f"(f.x), "f"(f.y));
    asm("add.rn.f32x2 %0, %0, %1;" : "+l"(acc) : "l"(v));
}
// pairwise fp16 add of two rows, then packed fp32 accumulate
__device__ __forceinline__ void acc_u4_pair_x2(unsigned long long* aa, uint4 v0, uint4 v1) {
    const __half2* h0 = (const __half2*)&v0;
    const __half2* h1 = (const __half2*)&v1;
    accx2(aa[0], __hadd2(h0[0], h1[0]));
    accx2(aa[1], __hadd2(h0[1], h1[1]));
    accx2(aa[2], __hadd2(h0[2], h1[2]));
    accx2(aa[3], __hadd2(h0[3], h1[3]));
}

// -------- fused prep (f2h + weight packing) + hist, block-range split --------
#define NG2   (NGn * 32)
#define ND2   (NDn * 32)
#define NWP   (4 * 2048)
#define PREP_ITEMS (NG2 + ND2 + NWP)
#define PREP_BLOCKS ((PREP_ITEMS + 255) / 256)
__global__ __launch_bounds__(256) void prep_hist(
    const float2* __restrict__ gene, __half2* __restrict__ geneH,
    const float2* __restrict__ dis,  __half2* __restrict__ disH,
    const float* __restrict__ w0, const float* __restrict__ w1,
    const float* __restrict__ w2, const float* __restrict__ w3,
    const float* __restrict__ w4, const float* __restrict__ w5,
    const float* __restrict__ w6, const float* __restrict__ w7,
    uint2* __restrict__ wPack,
    const int* __restrict__ src, const int* __restrict__ dst, int ne)
{
    int blk = blockIdx.x;
    if (blk < PREP_BLOCKS) {
        int i = blk * 256 + threadIdx.x;
        if (i < NG2) {
            float2 v = gene[i];
            geneH[i] = __floats2half2_rn(v.x, v.y);
        } else if (i < NG2 + ND2) {
            int j = i - NG2;
            float2 v = dis[j];
            disH[j] = __floats2half2_rn(v.x, v.y);
        } else if (i < PREP_ITEMS) {
            int p = i - (NG2 + ND2);
            int pi  = p >> 11;
            int rem = p & 2047;
            const float* wl;
            const float* wr;
            if      (pi == 0) { wl = w0; wr = w1; }
            else if (pi == 1) { wl = w2; wr = w3; }
            else if (pi == 2) { wl = w4; wr = w5; }
            else              { wl = w6; wr = w7; }
            int kc   = rem >> 8;
            int nt   = (rem >> 5) & 7;
            int lane = rem & 31;
            int t = lane & 3, g = lane >> 2;
            int c = nt * 8 + g;
            int k0 = kc * 16;
            int r0 = k0 + 2 * t, r2 = r0 + 8;
            float w00 = (r0 < 64)     ? wl[r0 * 64 + c]       : wr[(r0 - 64) * 64 + c];
            float w01 = (r0 + 1 < 64) ? wl[(r0 + 1) * 64 + c] : wr[(r0 - 63) * 64 + c];
            float w10 = (r2 < 64)     ? wl[r2 * 64 + c]       : wr[(r2 - 64) * 64 + c];
            float w11 = (r2 + 1 < 64) ? wl[(r2 + 1) * 64 + c] : wr[(r2 - 63) * 64 + c];
            wPack[p] = make_uint2(packh2(w00, w01), packh2(w10, w11));
        }
    } else {
        int e = (blk - PREP_BLOCKS) * 256 + threadIdx.x;
        if (e < ne) {
            atomicAdd(&g_deg[src[e]], 1);
            atomicAdd(&g_deg[NGn + dst[e]], 1);
        }
    }
}

// -------- single-pass scan (padded to 4/node) + sentinel fill --------
__global__ __launch_bounds__(1024) void scan_fused(
    int* __restrict__ off, int* __restrict__ cur, int* __restrict__ adj, int n)
{
    __shared__ int ws[32];
    __shared__ int sv[128];
    __shared__ int sExc;
    int bid = blockIdx.x;
    int tid = threadIdx.x;
    int i = bid * SCAN_B + tid;
    int v = (i < n) ? g_deg[i] : 0;
    int vp = (v + 3) & ~3;              // padded degree
    int x = vp;
    #pragma unroll
    for (int o = 1; o < 32; o <<= 1) {
        int y = __shfl_up_sync(0xFFFFFFFFu, x, o);
        if ((tid & 31) >= o) x += y;
    }
    if ((tid & 31) == 31) ws[tid >> 5] = x;
    __syncthreads();
    if (tid < 32) {
        int y = ws[tid];
        #pragma unroll
        for (int o = 1; o < 32; o <<= 1) {
            int z = __shfl_up_sync(0xFFFFFFFFu, y, o);
            if (tid >= o) y += z;
        }
        ws[tid] = y;
    }
    __syncthreads();
    if (tid >= 32) x += ws[(tid >> 5) - 1];
    if (tid == 1023) {
        atomicExch(&g_partf[bid], (x << 1) | 1);
    }
    if (tid < 128) sv[tid] = 0;
    __syncthreads();
    if (tid < bid) {
        int p;
        do { p = *(volatile int*)&g_partf[tid]; } while ((p & 1) == 0);
        sv[tid] = p >> 1;
    }
    __syncthreads();
    if (tid < 64) sv[tid] += sv[tid + 64];
    __syncthreads();
    if (tid < 32) {
        int s = sv[tid] + sv[tid + 32];
        #pragma unroll
        for (int o = 16; o; o >>= 1) s += __shfl_down_sync(0xFFFFFFFFu, s, o);
        if (tid == 0) sExc = s;
    }
    __syncthreads();
    if (i < n) {
        int inc = x + sExc;
        off[i + 1] = inc;
        int start = inc - vp;
        cur[i] = start;
        // fill padding with sentinel offsets (zero-row of the table this node reads)
        int sent = (i < NGn) ? (NDn << 7) : (NGn << 7);
        for (int k = v; k < vp; k++) adj[start + k] = sent;
        if (i == 0) off[0] = 0;
    }
}

// -------- scatter (stores PRE-SCALED byte offsets) --------
__global__ void scatter_kernel(const int* __restrict__ src, const int* __restrict__ dst,
                               int* __restrict__ cur, int* __restrict__ adj, int ne) {
    int e = blockIdx.x * blockDim.x + threadIdx.x;
    if (e < ne) {
        int s = src[e], d = dst[e];
        int p = atomicAdd(&cur[s], 1);        adj[p] = d << 7;
        int q = atomicAdd(&cur[NGn + d], 1);  adj[q] = s << 7;
    }
}

// -------- gather-mean: 4 nodes/warp, 8-lane group per node, no shuffles --------
// lane = g*8 + l: group g owns node warp*4+g; sublane l owns one 16B row slice.
// Segments are padded to multiples of 4 with zero-row sentinels: unconditional
// int4 index quads, no tails, no predication.
__global__ __launch_bounds__(256) void gather_h(
    const char* __restrict__ xgB, const char* __restrict__ xdB,
    const int* __restrict__ off, const int* __restrict__ adj,
    uint4* __restrict__ outG, uint4* __restrict__ outD)
{
    int warp = (blockIdx.x * blockDim.x + threadIdx.x) >> 5;
    if (warp * 4 >= Mn) return;
    int g = (threadIdx.x >> 3) & 3;
    int l = threadIdx.x & 7;
    int w = warp * 4 + g;                    // Mn % 4 == 0, always valid
    int beg = off[w], end = off[w + 1];
    int deg = __ldg(&g_deg[w]);
    const char* __restrict__ xb = ((w < NGn) ? xdB : xgB) + (l << 4);
    const int4* __restrict__ a4 = (const int4*)(adj + beg);
    int trips = (end - beg) >> 2;

    unsigned long long aa[4];
    {
        unsigned long long z;
        asm("mov.b64 %0, {%1, %2};" : "=l"(z) : "f"(0.0f), "f"(0.0f));
        aa[0] = z; aa[1] = z; aa[2] = z; aa[3] = z;
    }
    int qi = 0;
    for (; qi + 2 <= trips; qi += 2) {
        int4 q0 = __ldg(&a4[qi]);
        int4 q1 = __ldg(&a4[qi + 1]);
        uint4 v0 = *(const uint4*)(xb + q0.x);
        uint4 v1 = *(const uint4*)(xb + q0.y);
        uint4 v2 = *(const uint4*)(xb + q0.z);
        uint4 v3 = *(const uint4*)(xb + q0.w);
        uint4 v4 = *(const uint4*)(xb + q1.x);
        uint4 v5 = *(const uint4*)(xb + q1.y);
        uint4 v6 = *(const uint4*)(xb + q1.z);
        uint4 v7 = *(const uint4*)(xb + q1.w);
        acc_u4_pair_x2(aa, v0, v1);
        acc_u4_pair_x2(aa, v2, v3);
        acc_u4_pair_x2(aa, v4, v5);
        acc_u4_pair_x2(aa, v6, v7);
    }
    if (qi < trips) {
        int4 q = __ldg(&a4[qi]);
        uint4 v0 = *(const uint4*)(xb + q.x);
        uint4 v1 = *(const uint4*)(xb + q.y);
        uint4 v2 = *(const uint4*)(xb + q.z);
        uint4 v3 = *(const uint4*)(xb + q.w);
        acc_u4_pair_x2(aa, v0, v1);
        acc_u4_pair_x2(aa, v2, v3);
    }

    float2 a0, a1, a2, a3;
    asm("mov.b64 {%0, %1}, %2;" : "=f"(a0.x), "=f"(a0.y) : "l"(aa[0]));
    asm("mov.b64 {%0, %1}, %2;" : "=f"(a1.x), "=f"(a1.y) : "l"(aa[1]));
    asm("mov.b64 {%0, %1}, %2;" : "=f"(a2.x), "=f"(a2.y) : "l"(aa[2]));
    asm("mov.b64 {%0, %1}, %2;" : "=f"(a3.x), "=f"(a3.y) : "l"(aa[3]));
    float inv = 1.0f / fmaxf((float)deg, 1.0f);
    uint4 o;
    o.x = packh2(a0.x * inv, a0.y * inv);
    o.y = packh2(a1.x * inv, a1.y * inv);
    o.z = packh2(a2.x * inv, a2.y * inv);
    o.w = packh2(a3.x * inv, a3.y * inv);
    if (w < NGn) outG[(size_t)w * 8 + l] = o;
    else         outD[(size_t)(w - NGn) * 8 + l] = o;
}

// -------- persistent per-layer SAGE linear: smem-staged A + pre-packed fp16 B --------
#define LIN_GRID 592
__global__ __launch_bounds__(256) void sage_mma2(
    const uint4* __restrict__ mD4, const uint4* __restrict__ xD4,
    const uint2* __restrict__ wpD, const float* __restrict__ bDp,
    __half2* __restrict__ outDh, int nD,
    const uint4* __restrict__ mG4, const uint4* __restrict__ xG4,
    const uint2* __restrict__ wpG, const float* __restrict__ bGp,
    __half2* __restrict__ outGh, int nG,
    int relu)
{
    __shared__ uint2 sB[2048];
    __shared__ float sBias[64];
    __shared__ uint32_t sA[128][36];

    int nbD = (nD + 127) / 128;
    int nbG = (nG + 127) / 128;
    int split = (int)(((long long)LIN_GRID * nbD) / (nbD + nbG));
    if (split < 1) split = 1;
    bool isD = ((int)blockIdx.x < split);
    const uint4* mean4  = isD ? mD4 : mG4;
    const uint4* x4     = isD ? xD4 : xG4;
    const uint2* wp     = isD ? wpD : wpG;
    const float* bias   = isD ? bDp : bGp;
    __half2* out_h      = isD ? outDh : outGh;
    int n               = isD ? nD : nG;
    int nTiles          = isD ? nbD : nbG;
    int blk0            = isD ? blockIdx.x : (blockIdx.x - split);
    int nBlkSeg         = isD ? split : (LIN_GRID - split);

    int tid = threadIdx.x;

    for (int i = tid; i < 2048; i += 256) sB[i] = __ldg(&wp[i]);
    if (tid < 64) sBias[tid] = bias[tid];

    int warp = tid >> 5, lane = tid & 31;
    int t = lane & 3, g = lane >> 2;
    int la = warp * 16 + g, lb = la + 8;

    for (int blk = blk0; blk < nTiles; blk += nBlkSeg) {
        int tileBase = blk * 128;
        int ra = tileBase + la, rb = tileBase + lb;
        bool va = ra < n, vb = rb < n;

        float c_[8][4];

        __syncthreads();
        #pragma unroll
        for (int r4 = 0; r4 < 4; r4++) {
            int flat = tid + r4 * 256;
            int row = flat >> 3, c4 = flat & 7;
            int gr = tileBase + row;
            uint4 v = __ldg(&mean4[(size_t)(gr < n ? gr : 0) * 8 + c4]);
            *(uint4*)&sA[row][c4 * 4] = v;
        }
        __syncthreads();

        #pragma unroll
        for (int nt = 0; nt < 8; nt++) {
            float b0 = sBias[nt * 8 + 2 * t];
            float b1 = sBias[nt * 8 + 2 * t + 1];
            c_[nt][0] = b0; c_[nt][1] = b1; c_[nt][2] = b0; c_[nt][3] = b1;
        }

        #pragma unroll
        for (int kc = 0; kc < 4; kc++) {
            int b8 = kc * 8;
            uint32_t a0 = sA[la][b8 + t];
            uint32_t a1 = sA[lb][b8 + t];
            uint32_t a2 = sA[la][b8 + t + 4];
            uint32_t a3 = sA[lb][b8 + t + 4];
            #pragma unroll
            for (int nt = 0; nt < 8; nt++) {
                uint2 B = sB[kc * 256 + nt * 32 + lane];
                mma16(c_[nt], a0, a1, a2, a3, B.x, B.y);
            }
        }

        __syncthreads();
        #pragma unroll
        for (int r4 = 0; r4 < 4; r4++) {
            int flat = tid + r4 * 256;
            int row = flat >> 3, c4 = flat & 7;
            int gr = tileBase + row;
            uint4 v = __ldg(&x4[(size_t)(gr < n ? gr : 0) * 8 + c4]);
            *(uint4*)&sA[row][c4 * 4] = v;
        }
        __syncthreads();

        #pragma unroll
        for (int kc = 4; kc < 8; kc++) {
            int b8 = (kc & 3) * 8;
            uint32_t a0 = sA[la][b8 + t];
            uint32_t a1 = sA[lb][b8 + t];
            uint32_t a2 = sA[la][b8 + t + 4];
            uint32_t a3 = sA[lb][b8 + t + 4];
            #pragma unroll
            for (int nt = 0; nt < 8; nt++) {
                uint2 B = sB[kc * 256 + nt * 32 + lane];
                mma16(c_[nt], a0, a1, a2, a3, B.x, B.y);
            }
        }

        #pragma unroll
        for (int nt = 0; nt < 8; nt++) {
            float c0 = c_[nt][0], c1 = c_[nt][1], c2 = c_[nt][2], c3 = c_[nt][3];
            if (relu) {
                c0 = fmaxf(c0, 0.f); c1 = fmaxf(c1, 0.f);
                c2 = fmaxf(c2, 0.f); c3 = fmaxf(c3, 0.f);
            }
            if (va) out_h[(size_t)ra * 32 + nt * 4 + t] = __floats2half2_rn(c0, c1);
            if (vb) out_h[(size_t)rb * 32 + nt * 4 + t] = __floats2half2_rn(c2, c3);
        }
    }
}

// -------- label-edge dot product + restore deg/partf zero-invariant --------
__global__ __launch_bounds__(256) void dot_h(
    const __half2* __restrict__ hg2, const __half2* __restrict__ hd2,
    const int* __restrict__ ls, const int* __restrict__ ld,
    float* __restrict__ out, int nl)
{
    int t = blockIdx.x * blockDim.x + threadIdx.x;
    if (t < Mn) g_deg[t] = 0;          // last kernel: restore invariant
    if (t < 128) g_partf[t] = 0;
    int e = t >> 3;
    if (e >= nl) return;
    int lane = t & 7;
    int a = ls[e];
    int b = ld[e];
    const uint4* pg = (const uint4*)(hg2 + (size_t)a * 32);
    const uint4* pd = (const uint4*)(hd2 + (size_t)b * 32);
    uint4 G = __ldg(&pg[lane]);
    uint4 D = __ldg(&pd[lane]);

    float acc = 0.f;
    {
        float2 g0 = __half22float2(*(__half2*)&G.x), d0 = __half22float2(*(__half2*)&D.x);
        float2 g1 = __half22float2(*(__half2*)&G.y), d1 = __half22float2(*(__half2*)&D.y);
        float2 g2 = __half22float2(*(__half2*)&G.z), d2 = __half22float2(*(__half2*)&D.z);
        float2 g3 = __half22float2(*(__half2*)&G.w), d3 = __half22float2(*(__half2*)&D.w);
        acc = g0.x * d0.x + g0.y * d0.y + g1.x * d1.x + g1.y * d1.y
            + g2.x * d2.x + g2.y * d2.y + g3.x * d3.x + g3.y * d3.y;
    }
    acc += __shfl_down_sync(0xFFFFFFFFu, acc, 4);
    acc += __shfl_down_sync(0xFFFFFFFFu, acc, 2);
    acc += __shfl_down_sync(0xFFFFFFFFu, acc, 1);
    if (lane == 0) out[e] = acc;
}

extern "C" void kernel_launch(void* const* d_in, const int* in_sizes, int n_in,
                              void* d_out, int out_size)
{
    const float* gene = nullptr;
    const float* dis  = nullptr;
    const float* w[8] = {};
    const float* b[4] = {};
    const int*   edge[2] = {};
    const int*   lab[2]  = {};
    int wi = 0, bi = 0, ei = 0, li = 0;
    int ne = 0, nl = 0;

    for (int i = 0; i < n_in; i++) {
        int sz = in_sizes[i];
        if (sz == NGn * H)          gene = (const float*)d_in[i];
        else if (sz == NDn * H)     dis  = (const float*)d_in[i];
        else if (sz == H * H)       { if (wi < 8) w[wi++] = (const float*)d_in[i]; }
        else if (sz == H)           { if (bi < 4) b[bi++] = (const float*)d_in[i]; }
        else if (sz == 1500000)     { if (ei < 2) { edge[ei++] = (const int*)d_in[i]; ne = sz; } }
        else if (sz == 500000)      { if (li < 2) { lab[li++]  = (const int*)d_in[i]; nl = sz; } }
    }

    int *off, *cur, *adj;
    __half2 *geneH, *disH, *hgH, *hdH, *mGH, *mDH;
    uint2 *wPack;
    cudaGetSymbolAddress((void**)&off,   g_off);
    cudaGetSymbolAddress((void**)&cur,   g_cur);
    cudaGetSymbolAddress((void**)&adj,   g_adj);
    cudaGetSymbolAddress((void**)&geneH, g_geneH);
    cudaGetSymbolAddress((void**)&disH,  g_disH);
    cudaGetSymbolAddress((void**)&hgH,   g_hgH);
    cudaGetSymbolAddress((void**)&hdH,   g_hdH);
    cudaGetSymbolAddress((void**)&mGH,   g_mGH);
    cudaGetSymbolAddress((void**)&mDH,   g_mDH);
    cudaGetSymbolAddress((void**)&wPack, g_wPack);

    int egrid = (ne + 255) / 256;
    int ggrid = (Mn * 8 + 255) / 256;         // 4 nodes per warp
    int ph_grid = PREP_BLOCKS + egrid;

    // ---- fused prep+hist -> padded scan (+sentinels) -> scatter ----
    prep_hist<<<ph_grid, 256>>>(
        (const float2*)gene, geneH, (const float2*)dis, disH,
        w[0], w[1], w[2], w[3], w[4], w[5], w[6], w[7], wPack,
        edge[0], edge[1], ne);
    scan_fused<<<NBLK, 1024>>>(off, cur, adj, Mn);
    scatter_kernel<<<egrid, 256>>>(edge[0], edge[1], cur, adj, ne);

    // ---- layer 1 ----
    gather_h<<<ggrid, 256>>>((const char*)geneH, (const char*)disH, off, adj,
                             (uint4*)mGH, (uint4*)mDH);
    sage_mma2<<<LIN_GRID, 256>>>(
        (const uint4*)mDH, (const uint4*)disH,  wPack + 0,    b[0], hdH, NDn,
        (const uint4*)mGH, (const uint4*)geneH, wPack + 2048, b[1], hgH, NGn, 1);

    // ---- layer 2 (fp16 outputs written in-place over hgH/hdH) ----
    gather_h<<<ggrid, 256>>>((const char*)hgH, (const char*)hdH, off, adj,
                             (uint4*)mGH, (uint4*)mDH);
    sage_mma2<<<LIN_GRID, 256>>>(
        (const uint4*)mDH, (const uint4*)hdH, wPack + 4096, b[2], hdH, NDn,
        (const uint4*)mGH, (const uint4*)hgH, wPack + 6144, b[3], hgH, NGn, 0);

    // ---- classifier (also restores deg/partf invariants) ----
    int dot_grid = (nl * 8 + 255) / 256;
    dot_h<<<dot_grid, 256>>>(hgH, hdH, lab[0], lab[1], (float*)d_out, nl);
}